// round 1
// baseline (speedup 1.0000x reference)
#include <cuda_runtime.h>
#include <math.h>

#define BSZ 4
#define NN 4096
#define FD 256
#define LRALPHA 0.2f
#define ZSPLIT 8

// Scratch (static device globals — allocation-free per harness rules)
__device__ float g_h[BSZ * NN * FD];
__device__ float g_hn[BSZ * NN * FD];
__device__ float g_f1[BSZ * NN];
__device__ float g_f2[BSZ * NN];
__device__ float g_Zp[ZSPLIT][BSZ * NN];

// ---------------------------------------------------------------------------
// K1: h = input @ W   ([BSZ*NN, FD] x [FD, FD])
// 64x64 block tile, 256 threads, 4x4 micro-tile, K-chunk 16
// ---------------------------------------------------------------------------
__global__ __launch_bounds__(256) void k_gemm_h(const float* __restrict__ X,
                                                const float* __restrict__ W) {
    __shared__ float As[16][65];
    __shared__ float Bs[16][68];
    const int bm = blockIdx.y * 64;
    const int bn = blockIdx.x * 64;
    const int t = threadIdx.x;
    const int tx = t & 15, ty = t >> 4;
    float acc[4][4] = {};

    for (int k0 = 0; k0 < FD; k0 += 16) {
#pragma unroll
        for (int r = 0; r < 4; r++) {
            int idx = t + r * 256;
            int m = idx >> 4, k = idx & 15;
            As[k][m] = X[(size_t)(bm + m) * FD + k0 + k];
        }
#pragma unroll
        for (int r = 0; r < 4; r++) {
            int idx = t + r * 256;
            int k = idx >> 6, n = idx & 63;
            Bs[k][n] = W[(size_t)(k0 + k) * FD + bn + n];
        }
        __syncthreads();
#pragma unroll
        for (int kk = 0; kk < 16; kk++) {
            float av[4], bv[4];
#pragma unroll
            for (int i = 0; i < 4; i++) av[i] = As[kk][ty * 4 + i];
#pragma unroll
            for (int j = 0; j < 4; j++) bv[j] = Bs[kk][tx * 4 + j];
#pragma unroll
            for (int i = 0; i < 4; i++)
#pragma unroll
                for (int j = 0; j < 4; j++)
                    acc[i][j] = fmaf(av[i], bv[j], acc[i][j]);
        }
        __syncthreads();
    }
#pragma unroll
    for (int i = 0; i < 4; i++)
#pragma unroll
        for (int j = 0; j < 4; j++)
            g_h[(size_t)(bm + ty * 4 + i) * FD + bn + tx * 4 + j] = acc[i][j];
}

// ---------------------------------------------------------------------------
// K2: f1 = h . a1, f2 = h . a2   (one warp per row)
// ---------------------------------------------------------------------------
__global__ __launch_bounds__(256) void k_f12(const float* __restrict__ avec) {
    const int row = blockIdx.x * 8 + (threadIdx.x >> 5);
    const int lane = threadIdx.x & 31;
    const float* hr = g_h + (size_t)row * FD;
    float s1 = 0.f, s2 = 0.f;
#pragma unroll
    for (int k = lane; k < FD; k += 32) {
        float hv = hr[k];
        s1 = fmaf(hv, avec[k], s1);
        s2 = fmaf(hv, avec[FD + k], s2);
    }
#pragma unroll
    for (int o = 16; o > 0; o >>= 1) {
        s1 += __shfl_xor_sync(0xffffffffu, s1, o);
        s2 += __shfl_xor_sync(0xffffffffu, s2, o);
    }
    if (lane == 0) { g_f1[row] = s1; g_f2[row] = s2; }
}

// ---------------------------------------------------------------------------
// K3: per-column partial softmax denominators
// Zp[split][b,j] = sum_{i in split} adj[b,i,j]>0 ? exp(lrelu(f1_i+f2_j)) : 0
// ---------------------------------------------------------------------------
__global__ __launch_bounds__(128) void k_Z(const int* __restrict__ adj) {
    const int b = blockIdx.z;
    const int j = blockIdx.x * 128 + threadIdx.x;
    const int split = blockIdx.y;
    const int ilen = NN / ZSPLIT;
    const int i0 = split * ilen;
    const float f2j = g_f2[b * NN + j];
    const int* ap = adj + ((size_t)b * NN + i0) * NN + j;
    const float* f1p = g_f1 + b * NN + i0;
    float acc = 0.f;
#pragma unroll 8
    for (int i = 0; i < ilen; i++) {
        int m = ap[(size_t)i * NN];
        float s = f1p[i] + f2j;
        float l = fmaxf(s, LRALPHA * s);
        if (m > 0) acc += __expf(l);
    }
    g_Zp[split][b * NN + j] = acc;
}

// ---------------------------------------------------------------------------
// K3b: hn[row, :] = h[row, :] / Z[row]   (Z reduced from partials)
// ---------------------------------------------------------------------------
__global__ __launch_bounds__(64) void k_hn() {
    const int row = blockIdx.x;
    float z = 0.f;
#pragma unroll
    for (int s = 0; s < ZSPLIT; s++) z += g_Zp[s][row];
    const float zi = 1.0f / z;
    const float4* hp = (const float4*)(g_h + (size_t)row * FD);
    float4* hnp = (float4*)(g_hn + (size_t)row * FD);
    float4 v = hp[threadIdx.x];
    v.x *= zi; v.y *= zi; v.z *= zi; v.w *= zi;
    hnp[threadIdx.x] = v;
}

// ---------------------------------------------------------------------------
// K4: out = elu( W_mask @ hn )
//   W_mask[i,j] = adj[b,i,j]>0 ? exp(lrelu(f1_i+f2_j)) : 0, built on the fly.
// 128(i) x 128(f) block tile, 256 threads, 8x8 micro-tile, j-chunk 16.
// ---------------------------------------------------------------------------
__global__ __launch_bounds__(256, 2) void k_main(const int* __restrict__ adj,
                                                 float* __restrict__ out) {
    __shared__ float Ws[16][128];
    __shared__ float Hs[16][128];
    __shared__ float f1s[128];

    const int b = blockIdx.z;
    const int i0 = blockIdx.y * 128;
    const int f0 = blockIdx.x * 128;
    const int t = threadIdx.x;
    const int tx = t & 15, ty = t >> 4;

    if (t < 128) f1s[t] = g_f1[b * NN + i0 + t];

    // per-thread staging roles
    const int wii = t >> 1;            // 0..127 : row within i-tile for W build
    const int wj0 = (t & 1) * 8;       // 0 or 8 : j-subchunk for W build
    const int hjj = t >> 4;            // 0..15  : row within j-chunk for H load
    const int hf0 = (t & 15) * 8;      // f-offset for H load

    const int* adjb = adj + ((size_t)b * NN + i0 + wii) * NN + wj0;
    const float* f2b = g_f2 + b * NN + wj0;
    const float* hnb = g_hn + ((size_t)b * NN + hjj) * FD + f0 + hf0;

    float acc[8][8] = {};

    for (int j0 = 0; j0 < NN; j0 += 16) {
        // ---- issue global loads before the barrier ----
        int4 m0 = *(const int4*)(adjb + j0);
        int4 m1 = *(const int4*)(adjb + j0 + 4);
        float f2r[8];
#pragma unroll
        for (int q = 0; q < 8; q++) f2r[q] = f2b[j0 + q];
        float4 h0 = *(const float4*)(hnb + (size_t)j0 * FD);
        float4 h1 = *(const float4*)(hnb + (size_t)j0 * FD + 4);

        __syncthreads();  // previous FMA phase done reading smem

        const float f1v = f1s[wii];
        int mm[8] = {m0.x, m0.y, m0.z, m0.w, m1.x, m1.y, m1.z, m1.w};
#pragma unroll
        for (int q = 0; q < 8; q++) {
            float s = f1v + f2r[q];
            float l = fmaxf(s, LRALPHA * s);
            Ws[wj0 + q][wii] = (mm[q] > 0) ? __expf(l) : 0.f;
        }
        *(float4*)(&Hs[hjj][hf0])     = h0;
        *(float4*)(&Hs[hjj][hf0 + 4]) = h1;

        __syncthreads();

#pragma unroll
        for (int jj = 0; jj < 16; jj++) {
            float av[8], bv[8];
            *(float4*)(av)     = *(const float4*)(&Ws[jj][ty * 8]);
            *(float4*)(av + 4) = *(const float4*)(&Ws[jj][ty * 8 + 4]);
            *(float4*)(bv)     = *(const float4*)(&Hs[jj][tx * 8]);
            *(float4*)(bv + 4) = *(const float4*)(&Hs[jj][tx * 8 + 4]);
#pragma unroll
            for (int i = 0; i < 8; i++)
#pragma unroll
                for (int jx = 0; jx < 8; jx++)
                    acc[i][jx] = fmaf(av[i], bv[jx], acc[i][jx]);
        }
    }

    // epilogue: elu + vectorized store
#pragma unroll
    for (int i = 0; i < 8; i++) {
        const size_t orow = ((size_t)b * NN + i0 + ty * 8 + i) * FD + f0 + tx * 8;
        float o[8];
#pragma unroll
        for (int jx = 0; jx < 8; jx++) {
            float c = acc[i][jx];
            o[jx] = (c > 0.f) ? c : expm1f(c);
        }
        *(float4*)(out + orow)     = *(float4*)(o);
        *(float4*)(out + orow + 4) = *(float4*)(o + 4);
    }
}

// ---------------------------------------------------------------------------
extern "C" void kernel_launch(void* const* d_in, const int* in_sizes, int n_in,
                              void* d_out, int out_size) {
    const float* input = (const float*)d_in[0];   // [4,4096,256] f32
    const int*   adj   = (const int*)d_in[1];     // [4,4096,4096] i32
    const float* W     = (const float*)d_in[2];   // [256,256] f32
    const float* a     = (const float*)d_in[3];   // [512,1] f32
    float* out = (float*)d_out;

    k_gemm_h<<<dim3(FD / 64, (BSZ * NN) / 64), 256>>>(input, W);
    k_f12<<<(BSZ * NN) / 8, 256>>>(a);
    k_Z<<<dim3(NN / 128, ZSPLIT, BSZ), 128>>>(adj);
    k_hn<<<BSZ * NN, 64>>>();
    k_main<<<dim3(FD / 128, NN / 128, BSZ), 256>>>(adj, out);
}

// round 3
// speedup vs baseline: 1.7283x; 1.7283x over previous
#include <cuda_runtime.h>
#include <cstdint>
#include <math.h>

#define BSZ 4
#define NN 4096
#define FD 256
#define LRALPHA 0.2f
#define ZSPLIT 8

#define TM 128
#define KC 32
#define NCHUNK (NN / KC)

// shared memory layout (float offsets)
#define F2_OFF   0                       // 4096 floats (full f2 row)
#define A_STAGE  (32 * 136)              // [k][i] stride 136
#define A_OFF    4096
#define B_STAGE  (32 * 264)              // [k][n] stride 264
#define B_OFF    (4096 + 2 * A_STAGE)
#define SMEM_FLOATS (4096 + 2 * A_STAGE + 3 * B_STAGE)
#define SMEM_BYTES  (SMEM_FLOATS * 4)

// scratch
__device__ float g_h[BSZ * NN * FD];
__device__ float g_hn[BSZ * NN * FD];    // h / Z_j, tf32-rounded
__device__ float g_f1[BSZ * NN];
__device__ float g_f2[BSZ * NN];
__device__ float g_Zp[ZSPLIT][BSZ * NN];

// ---------------- helpers ----------------
__device__ __forceinline__ uint32_t smem_u32(const void* p) {
    uint32_t a;
    asm("{ .reg .u64 t; cvta.to.shared.u64 t, %1; cvt.u32.u64 %0, t; }" : "=r"(a) : "l"(p));
    return a;
}
__device__ __forceinline__ float tf32r(float x) {
    uint32_t r;
    asm("cvt.rna.tf32.f32 %0, %1;" : "=r"(r) : "f"(x));
    return __uint_as_float(r);
}
__device__ __forceinline__ void cp16(uint32_t dst, const float* src) {
    asm volatile("cp.async.cg.shared.global [%0], [%1], 16;" :: "r"(dst), "l"(src));
}
#define CP_COMMIT() asm volatile("cp.async.commit_group;" ::: "memory")
#define CP_WAIT1()  asm volatile("cp.async.wait_group 1;" ::: "memory")
#define CP_WAIT0()  asm volatile("cp.async.wait_group 0;" ::: "memory")

__device__ __forceinline__ void mma_tf32(float* d, const uint32_t* a, const uint32_t* bb) {
    asm volatile(
        "mma.sync.aligned.m16n8k8.row.col.f32.tf32.tf32.f32 "
        "{%0,%1,%2,%3}, {%4,%5,%6,%7}, {%8,%9}, {%0,%1,%2,%3};"
        : "+f"(d[0]), "+f"(d[1]), "+f"(d[2]), "+f"(d[3])
        : "r"(a[0]), "r"(a[1]), "r"(a[2]), "r"(a[3]), "r"(bb[0]), "r"(bb[1]));
}

// ---------------------------------------------------------------------------
// K1: h = input @ W  (fp32 SIMT, full precision for downstream f1/f2)
// ---------------------------------------------------------------------------
__global__ __launch_bounds__(256) void k_gemm_h(const float* __restrict__ X,
                                                const float* __restrict__ W) {
    __shared__ float As[16][65];
    __shared__ float Bs[16][68];
    const int bm = blockIdx.y * 64;
    const int bn = blockIdx.x * 64;
    const int t = threadIdx.x;
    const int tx = t & 15, ty = t >> 4;
    float acc[4][4] = {};
    for (int k0 = 0; k0 < FD; k0 += 16) {
#pragma unroll
        for (int r = 0; r < 4; r++) {
            int idx = t + r * 256;
            int m = idx >> 4, k = idx & 15;
            As[k][m] = X[(size_t)(bm + m) * FD + k0 + k];
        }
#pragma unroll
        for (int r = 0; r < 4; r++) {
            int idx = t + r * 256;
            int k = idx >> 6, n = idx & 63;
            Bs[k][n] = W[(size_t)(k0 + k) * FD + bn + n];
        }
        __syncthreads();
#pragma unroll
        for (int kk = 0; kk < 16; kk++) {
            float av[4], bv[4];
#pragma unroll
            for (int i = 0; i < 4; i++) av[i] = As[kk][ty * 4 + i];
#pragma unroll
            for (int j = 0; j < 4; j++) bv[j] = Bs[kk][tx * 4 + j];
#pragma unroll
            for (int i = 0; i < 4; i++)
#pragma unroll
                for (int j = 0; j < 4; j++)
                    acc[i][j] = fmaf(av[i], bv[j], acc[i][j]);
        }
        __syncthreads();
    }
#pragma unroll
    for (int i = 0; i < 4; i++)
#pragma unroll
        for (int j = 0; j < 4; j++)
            g_h[(size_t)(bm + ty * 4 + i) * FD + bn + tx * 4 + j] = acc[i][j];
}

// ---------------------------------------------------------------------------
// K2: f1 = h.a1, f2 = h.a2
// ---------------------------------------------------------------------------
__global__ __launch_bounds__(256) void k_f12(const float* __restrict__ avec) {
    const int row = blockIdx.x * 8 + (threadIdx.x >> 5);
    const int lane = threadIdx.x & 31;
    const float* hr = g_h + (size_t)row * FD;
    float s1 = 0.f, s2 = 0.f;
#pragma unroll
    for (int k = lane; k < FD; k += 32) {
        float hv = hr[k];
        s1 = fmaf(hv, avec[k], s1);
        s2 = fmaf(hv, avec[FD + k], s2);
    }
#pragma unroll
    for (int o = 16; o > 0; o >>= 1) {
        s1 += __shfl_xor_sync(0xffffffffu, s1, o);
        s2 += __shfl_xor_sync(0xffffffffu, s2, o);
    }
    if (lane == 0) { g_f1[row] = s1; g_f2[row] = s2; }
}

// ---------------------------------------------------------------------------
// K3: partial softmax denominators per column j (softmax is over i)
// ---------------------------------------------------------------------------
__global__ __launch_bounds__(128) void k_Z(const int* __restrict__ adj) {
    const int b = blockIdx.z;
    const int j = blockIdx.x * 128 + threadIdx.x;
    const int split = blockIdx.y;
    const int ilen = NN / ZSPLIT;
    const int i0 = split * ilen;
    const float f2j = g_f2[b * NN + j];
    const int* ap = adj + ((size_t)b * NN + i0) * NN + j;
    const float* f1p = g_f1 + b * NN + i0;
    float acc = 0.f;
#pragma unroll 8
    for (int i = 0; i < ilen; i++) {
        int m = ap[(size_t)i * NN];
        float s = f1p[i] + f2j;
        float l = fmaxf(s, LRALPHA * s);
        if (m > 0) acc += __expf(l);
    }
    g_Zp[split][b * NN + j] = acc;
}

// ---------------------------------------------------------------------------
// K3b: hn[j,:] = tf32( h[j,:] / Z_j )
// ---------------------------------------------------------------------------
__global__ __launch_bounds__(64) void k_hn() {
    const int row = blockIdx.x;
    float z = 0.f;
#pragma unroll
    for (int s = 0; s < ZSPLIT; s++) z += g_Zp[s][row];
    const float zi = 1.0f / z;
    const float4* hp = (const float4*)(g_h + (size_t)row * FD);
    float4* hnp = (float4*)(g_hn + (size_t)row * FD);
    float4 v = hp[threadIdx.x];
    v.x = tf32r(v.x * zi); v.y = tf32r(v.y * zi);
    v.z = tf32r(v.z * zi); v.w = tf32r(v.w * zi);
    hnp[threadIdx.x] = v;
}

// ---------------------------------------------------------------------------
// K4: out = elu( E @ hn ) via mma.sync tf32 (m16n8k8)
//   grid (NN/128, BSZ), 512 threads = 16 warps (2m x 8n), warp tile 64x32
// ---------------------------------------------------------------------------
__global__ void __launch_bounds__(512, 1) k_main_mma(const int* __restrict__ adj,
                                                     float* __restrict__ out) {
    extern __shared__ float sm[];
    const uint32_t smb = smem_u32(sm);
    const int t = threadIdx.x;
    const int wid = t >> 5, lane = t & 31;
    const int b = blockIdx.y;
    const int i0 = blockIdx.x * TM;

    const int wm = wid >> 3;        // 0..1
    const int wn = wid & 7;         // 0..7

    // builder roles
    const int ia = t & 127;         // A: i-row
    const int kh = (t >> 7) * 8;    // A: k sub-chunk (8 wide)
    const int kb = t >> 4;          // B: k-row (0..31)
    const int s16 = t & 15;         // B: 16B segment selector

    // cache f2 row (16KB)
#pragma unroll
    for (int q = 0; q < 2; q++)
        ((float4*)(sm + F2_OFF))[t + q * 512] = ((const float4*)(g_f2 + b * NN))[t + q * 512];

    const float f1v = g_f1[b * NN + i0 + ia];
    const int* ap0 = adj + ((size_t)(b * NN + i0 + ia)) * NN + kh;
    const float* hb = g_hn + (size_t)b * NN * FD;

    // B prefetch of chunks 0 and 1
#pragma unroll
    for (int c = 0; c < 2; c++) {
        const float* src = hb + (size_t)(c * KC + kb) * FD + s16 * 4;
        uint32_t dst = smb + (B_OFF + (c % 3) * B_STAGE + kb * 264 + s16 * 4) * 4;
#pragma unroll
        for (int q = 0; q < 4; q++)
            cp16(dst + q * 256, src + q * 64);
        CP_COMMIT();
    }
    __syncthreads();   // f2 cache ready

    float acc[4][4][4] = {};   // [mf][nf][reg]

    for (int c = 0; c < NCHUNK; c++) {
        const int aoff = A_OFF + (c & 1) * A_STAGE;
        const int boff = B_OFF + (c % 3) * B_STAGE;
        const int j0 = c * KC;

        // ---- build A: masked exp weights into [k][i] stride-136 ----
        int4 m0 = *(const int4*)(ap0 + j0);
        int4 m1 = *(const int4*)(ap0 + j0 + 4);
        int mm[8] = {m0.x, m0.y, m0.z, m0.w, m1.x, m1.y, m1.z, m1.w};
        float e[8];
#pragma unroll
        for (int q = 0; q < 8; q++) {
            float s = f1v + sm[F2_OFF + j0 + kh + q];
            float l = fmaxf(s, LRALPHA * s);
            e[q] = (mm[q] > 0) ? tf32r(__expf(l)) : 0.f;
        }
#pragma unroll
        for (int q = 0; q < 8; q++)
            sm[aoff + (kh + q) * 136 + ia] = e[q];

        // ---- wait B(c) ----
        if (c + 1 < NCHUNK) { CP_WAIT1(); } else { CP_WAIT0(); }
        __syncthreads();

        // ---- prefetch B(c+2) (safe: all warps past mma(c-1)) ----
        if (c + 2 < NCHUNK) {
            const float* src = hb + (size_t)((c + 2) * KC + kb) * FD + s16 * 4;
            uint32_t dst = smb + (B_OFF + ((c + 2) % 3) * B_STAGE + kb * 264 + s16 * 4) * 4;
#pragma unroll
            for (int q = 0; q < 4; q++)
                cp16(dst + q * 256, src + q * 64);
            CP_COMMIT();
        }

        // ---- mma over k-frags ----
        const uint32_t* smu = (const uint32_t*)sm;
#pragma unroll
        for (int kf = 0; kf < 4; kf++) {
            const int krow = kf * 8 + (lane & 3);
            uint32_t a[4][4];
#pragma unroll
            for (int mf = 0; mf < 4; mf++) {
                int base = aoff + krow * 136 + wm * 64 + mf * 16 + (lane >> 2);
                a[mf][0] = smu[base];
                a[mf][1] = smu[base + 8];
                a[mf][2] = smu[base + 4 * 136];
                a[mf][3] = smu[base + 4 * 136 + 8];
            }
            uint32_t bf[4][2];
#pragma unroll
            for (int nf = 0; nf < 4; nf++) {
                int base = boff + krow * 264 + wn * 32 + nf * 8 + (lane >> 2);
                bf[nf][0] = smu[base];
                bf[nf][1] = smu[base + 4 * 264];
            }
#pragma unroll
            for (int mf = 0; mf < 4; mf++)
#pragma unroll
                for (int nf = 0; nf < 4; nf++)
                    mma_tf32(acc[mf][nf], a[mf], bf[nf]);
        }
    }

    // ---- epilogue: ELU + float2 stores ----
#pragma unroll
    for (int mf = 0; mf < 4; mf++) {
        const int r0 = i0 + wm * 64 + mf * 16 + (lane >> 2);
#pragma unroll
        for (int nf = 0; nf < 4; nf++) {
            const int c0 = wn * 32 + nf * 8 + 2 * (lane & 3);
            float v0 = acc[mf][nf][0], v1 = acc[mf][nf][1];
            float v2 = acc[mf][nf][2], v3 = acc[mf][nf][3];
            float2 p0 = make_float2(v0 > 0.f ? v0 : expm1f(v0),
                                    v1 > 0.f ? v1 : expm1f(v1));
            float2 p1 = make_float2(v2 > 0.f ? v2 : expm1f(v2),
                                    v3 > 0.f ? v3 : expm1f(v3));
            *(float2*)(out + ((size_t)(b * NN + r0)) * FD + c0) = p0;
            *(float2*)(out + ((size_t)(b * NN + r0 + 8)) * FD + c0) = p1;
        }
    }
}

// ---------------------------------------------------------------------------
extern "C" void kernel_launch(void* const* d_in, const int* in_sizes, int n_in,
                              void* d_out, int out_size) {
    const float* input = (const float*)d_in[0];
    const int*   adj   = (const int*)d_in[1];
    const float* W     = (const float*)d_in[2];
    const float* a     = (const float*)d_in[3];
    float* out = (float*)d_out;

    static int configured = 0;
    if (!configured) {
        cudaFuncSetAttribute(k_main_mma, cudaFuncAttributeMaxDynamicSharedMemorySize, SMEM_BYTES);
        configured = 1;
    }

    k_gemm_h<<<dim3(FD / 64, (BSZ * NN) / 64), 256>>>(input, W);
    k_f12<<<(BSZ * NN) / 8, 256>>>(a);
    k_Z<<<dim3(NN / 128, ZSPLIT, BSZ), 128>>>(adj);
    k_hn<<<BSZ * NN, 64>>>();
    k_main_mma<<<dim3(NN / TM, BSZ), 512, SMEM_BYTES>>>(adj, out);
}

// round 4
// speedup vs baseline: 2.0646x; 1.1946x over previous
#include <cuda_runtime.h>
#include <cstdint>
#include <math.h>

#define BSZ 4
#define NN 4096
#define FD 256
#define NCH (NN / 32)
#define LOG2E 1.4426950408889634f

// ---------------- scratch ----------------
__device__ float g_hn[BSZ * NN * FD];    // h / Z_j, tf32-rounded (GEMM B operand)
__device__ float g_f1[BSZ * NN];         // (X.(W a1)) * log2e
__device__ float g_f2[BSZ * NN];         // (X.(W a2)) * log2e
__device__ float g_Zp[8][BSZ * NN];
__device__ float g_v[2 * FD];            // W@a1*log2e, W@a2*log2e

// ---------------- helpers ----------------
__device__ __forceinline__ uint32_t smem_u32(const void* p) {
    uint32_t a;
    asm("{ .reg .u64 t; cvta.to.shared.u64 t, %1; cvt.u32.u64 %0, t; }" : "=r"(a) : "l"(p));
    return a;
}
__device__ __forceinline__ float tf32r(float x) {
    uint32_t r;
    asm("cvt.rna.tf32.f32 %0, %1;" : "=r"(r) : "f"(x));
    return __uint_as_float(r);
}
__device__ __forceinline__ void cp16(uint32_t dst, const float* src) {
    asm volatile("cp.async.cg.shared.global [%0], [%1], 16;" :: "r"(dst), "l"(src));
}
#define CP_COMMIT() asm volatile("cp.async.commit_group;" ::: "memory")
#define CP_WAIT0()  asm volatile("cp.async.wait_group 0;" ::: "memory")

// 2^y on the FMA pipe (no MUFU). |y| < 2^21, rel err ~2e-6.
__device__ __forceinline__ float fexp2(float y) {
    float yr = y + 12582912.0f;                      // 1.5 * 2^23 magic
    int n = __float_as_int(yr) - 0x4B400000;
    float r = y - (yr - 12582912.0f);                // r in [-0.5, 0.5]
    float p = fmaf(0.0013333558f, r, 0.0096181291f);
    p = fmaf(p, r, 0.0555041086f);
    p = fmaf(p, r, 0.2402265069f);
    p = fmaf(p, r, 0.6931471806f);
    p = fmaf(p, r, 1.0f);
    return __int_as_float(__float_as_int(p) + (n << 23));
}
// elu(x) without MUFU
__device__ __forceinline__ float felu(float x) {
    float q = fmaf(0.0083333338f, x, 0.0416666679f); // expm1 Taylor for small |x|
    q = fmaf(q, x, 0.16666667f);
    q = fmaf(q, x, 0.5f);
    q = fmaf(q, x, 1.0f);
    float small = x * q;
    float big = fexp2(x * LOG2E) - 1.0f;
    float neg = (x >= -0.25f) ? small : big;
    return (x > 0.f) ? x : neg;
}

__device__ __forceinline__ void mma_tf32(float* d, const uint32_t* a, const uint32_t* bb) {
    asm volatile(
        "mma.sync.aligned.m16n8k8.row.col.f32.tf32.tf32.f32 "
        "{%0,%1,%2,%3}, {%4,%5,%6,%7}, {%8,%9}, {%0,%1,%2,%3};"
        : "+f"(d[0]), "+f"(d[1]), "+f"(d[2]), "+f"(d[3])
        : "r"(a[0]), "r"(a[1]), "r"(a[2]), "r"(a[3]), "r"(bb[0]), "r"(bb[1]));
}

// ---------------------------------------------------------------------------
// K0: v1 = (W @ a1) * log2e, v2 = (W @ a2) * log2e   (tiny)
// ---------------------------------------------------------------------------
__global__ __launch_bounds__(256) void k_wa(const float* __restrict__ W,
                                            const float* __restrict__ a) {
    const int w = threadIdx.x >> 5, lane = threadIdx.x & 31;
    for (int r = w; r < FD; r += 8) {
        float s1 = 0.f, s2 = 0.f;
        for (int f = lane; f < FD; f += 32) {
            float wv = W[r * FD + f];
            s1 = fmaf(wv, a[f], s1);
            s2 = fmaf(wv, a[FD + f], s2);
        }
#pragma unroll
        for (int o = 16; o; o >>= 1) {
            s1 += __shfl_xor_sync(~0u, s1, o);
            s2 += __shfl_xor_sync(~0u, s2, o);
        }
        if (lane == 0) { g_v[r] = s1 * LOG2E; g_v[FD + r] = s2 * LOG2E; }
    }
}

// ---------------------------------------------------------------------------
// K1: f1 = X.v1, f2 = X.v2  (exact fp32; one warp per row)
// ---------------------------------------------------------------------------
__global__ __launch_bounds__(256) void k_f12(const float* __restrict__ X) {
    const int row = blockIdx.x * 8 + (threadIdx.x >> 5);
    const int lane = threadIdx.x & 31;
    const float* xr = X + (size_t)row * FD;
    float s1 = 0.f, s2 = 0.f;
#pragma unroll
    for (int k = lane; k < FD; k += 32) {
        float xv = xr[k];
        s1 = fmaf(xv, g_v[k], s1);
        s2 = fmaf(xv, g_v[FD + k], s2);
    }
#pragma unroll
    for (int o = 16; o; o >>= 1) {
        s1 += __shfl_xor_sync(~0u, s1, o);
        s2 += __shfl_xor_sync(~0u, s2, o);
    }
    if (lane == 0) { g_f1[row] = s1; g_f2[row] = s2; }
}

// ---------------------------------------------------------------------------
// K2: partial softmax denominators per column j (FMA-pipe exp)
// ---------------------------------------------------------------------------
__global__ __launch_bounds__(128) void k_Z(const int* __restrict__ adj) {
    const int b = blockIdx.z;
    const int j = blockIdx.x * 128 + threadIdx.x;
    const int split = blockIdx.y;
    const int ilen = NN / 8;
    const int i0 = split * ilen;
    const float f2j = g_f2[b * NN + j];
    const int* ap = adj + ((size_t)b * NN + i0) * NN + j;
    const float* f1p = g_f1 + b * NN + i0;
    float acc = 0.f;
#pragma unroll 8
    for (int i = 0; i < ilen; i++) {
        int m = ap[(size_t)i * NN];
        float y = f1p[i] + f2j;
        y = fmaxf(y, 0.2f * y);
        float e = fexp2(y);
        acc += (m > 0) ? e : 0.f;
    }
    g_Zp[split][b * NN + j] = acc;
}

// ---------------------------------------------------------------------------
// K3: hn = tf32( (X @ W) * (1/Z_row) )  via mma.sync tf32
//   CTA: 64 rows x 256 cols, 256 threads (8 warps 1x8), K=256 in 8 chunks
// ---------------------------------------------------------------------------
#define HG_ZI 0
#define HG_A 64
#define HG_ASTG (32 * 72)                 // 2304 floats
#define HG_B (64 + 2 * HG_ASTG)           // 4672
#define HG_BSTG (32 * 264)                // 8448 floats
#define HG_FLOATS (HG_B + 2 * HG_BSTG)    // 21568
__global__ void __launch_bounds__(256, 2) k_hgen(const float* __restrict__ X,
                                                 const float* __restrict__ W) {
    extern __shared__ float sm[];
    const uint32_t smb = smem_u32(sm);
    const int t = threadIdx.x, lane = t & 31, wn = t >> 5, g = lane >> 2;
    const int R0 = blockIdx.x * 64;
    const int ia = t & 63, kh = (t >> 6) * 8;
    const int kb = t >> 3, seg = t & 7;

    if (t < 64) {
        float z = 0.f;
#pragma unroll
        for (int s = 0; s < 8; s++) z += g_Zp[s][R0 + t];
        sm[HG_ZI + t] = 1.0f / z;
    }

    const float* xrow = X + (size_t)(R0 + ia) * FD + kh;
    // prefetch B(0) = W rows 0..31
    {
        const float* src = W + (size_t)kb * FD + seg * 4;
        uint32_t dst = smb + (HG_B + kb * 264 + seg * 4) * 4;
#pragma unroll
        for (int q = 0; q < 8; q++) cp16(dst + q * 128, src + q * 32);
        CP_COMMIT();
    }

    float acc[4][4][4] = {};
    for (int c = 0; c < 8; c++) {
        const int aoff = HG_A + (c & 1) * HG_ASTG;
        const int boff = HG_B + (c & 1) * HG_BSTG;
        float4 x0 = *(const float4*)(xrow + c * 32);
        float4 x1 = *(const float4*)(xrow + c * 32 + 4);
        float e[8] = {x0.x, x0.y, x0.z, x0.w, x1.x, x1.y, x1.z, x1.w};
#pragma unroll
        for (int q = 0; q < 8; q++)
            sm[aoff + (kh + q) * 72 + ia] = tf32r(e[q]);
        CP_WAIT0();
        __syncthreads();
        if (c < 7) {
            const float* src = W + (size_t)((c + 1) * 32 + kb) * FD + seg * 4;
            uint32_t dst = smb + (HG_B + ((c + 1) & 1) * HG_BSTG + kb * 264 + seg * 4) * 4;
#pragma unroll
            for (int q = 0; q < 8; q++) cp16(dst + q * 128, src + q * 32);
            CP_COMMIT();
        }
        const uint32_t* smu = (const uint32_t*)sm;
#pragma unroll
        for (int kf = 0; kf < 4; kf++) {
            const int krow = kf * 8 + (lane & 3);
            uint32_t a[4][4];
#pragma unroll
            for (int mf = 0; mf < 4; mf++) {
                int base = aoff + krow * 72 + mf * 16 + g;
                a[mf][0] = smu[base];
                a[mf][1] = smu[base + 8];
                a[mf][2] = smu[base + 4 * 72];
                a[mf][3] = smu[base + 4 * 72 + 8];
            }
            uint32_t bf[4][2];
#pragma unroll
            for (int nf = 0; nf < 4; nf++) {
                int base = boff + krow * 264 + wn * 32 + nf * 8 + g;
                bf[nf][0] = smu[base];
                bf[nf][1] = smu[base + 4 * 264];
            }
#pragma unroll
            for (int mf = 0; mf < 4; mf++)
#pragma unroll
                for (int nf = 0; nf < 4; nf++)
                    mma_tf32(acc[mf][nf], a[mf], bf[nf]);
        }
    }
    // epilogue: scale by 1/Z and round to tf32
#pragma unroll
    for (int mf = 0; mf < 4; mf++) {
        const int rl0 = mf * 16 + g;
        const float zi0 = sm[HG_ZI + rl0], zi1 = sm[HG_ZI + rl0 + 8];
#pragma unroll
        for (int nf = 0; nf < 4; nf++) {
            const int c0 = wn * 32 + nf * 8 + 2 * (lane & 3);
            float2 p0 = make_float2(tf32r(acc[mf][nf][0] * zi0), tf32r(acc[mf][nf][1] * zi0));
            float2 p1 = make_float2(tf32r(acc[mf][nf][2] * zi1), tf32r(acc[mf][nf][3] * zi1));
            *(float2*)(g_hn + (size_t)(R0 + rl0) * FD + c0) = p0;
            *(float2*)(g_hn + (size_t)(R0 + rl0 + 8) * FD + c0) = p1;
        }
    }
}

// ---------------------------------------------------------------------------
// K4: out = elu( E @ hn ),  E built on the fly with FMA-pipe exp.
//   CTA: 64(i) x 256(f), 256 threads, 2 CTAs/SM, 1 sync/chunk,
//   adj/f2 register-prefetch + 2-stage cp.async B ring.
// ---------------------------------------------------------------------------
#define KM_A 0
#define KM_ASTG 2304
#define KM_B (2 * KM_ASTG)                 // 4608
#define KM_BSTG 8448
#define KM_FLOATS (KM_B + 2 * KM_BSTG)     // 21504
__global__ void __launch_bounds__(256, 2) k_att(const int* __restrict__ adj,
                                                float* __restrict__ out) {
    extern __shared__ float sm[];
    const uint32_t smb = smem_u32(sm);
    const int t = threadIdx.x, lane = t & 31, wn = t >> 5, g = lane >> 2;
    const int b = blockIdx.y;
    const int i0 = blockIdx.x * 64;
    const int ia = t & 63, kh = (t >> 6) * 8;
    const int kb = t >> 3, seg = t & 7;

    const int* ap = adj + ((size_t)(b * NN + i0 + ia)) * NN + kh;
    const float* f2p = g_f2 + b * NN + kh;
    const float* hb = g_hn + (size_t)b * NN * FD;
    const float f1v = g_f1[b * NN + i0 + ia];

    // prefetch B(0)
    {
        const float* src = hb + (size_t)kb * FD + seg * 4;
        uint32_t dst = smb + (KM_B + kb * 264 + seg * 4) * 4;
#pragma unroll
        for (int q = 0; q < 8; q++) cp16(dst + q * 128, src + q * 32);
        CP_COMMIT();
    }
    // preload adj/f2 chunk 0
    int4 m0 = *(const int4*)(ap);
    int4 m1 = *(const int4*)(ap + 4);
    float4 fa = *(const float4*)(f2p);
    float4 fb = *(const float4*)(f2p + 4);

    float acc[4][4][4] = {};
    for (int c = 0; c < NCH; c++) {
        const int aoff = KM_A + (c & 1) * KM_ASTG;
        const int boff = KM_B + (c & 1) * KM_BSTG;

        int mm[8] = {m0.x, m0.y, m0.z, m0.w, m1.x, m1.y, m1.z, m1.w};
        float f2r[8] = {fa.x, fa.y, fa.z, fa.w, fb.x, fb.y, fb.z, fb.w};
#pragma unroll
        for (int q = 0; q < 8; q++) {
            float y = f1v + f2r[q];
            y = fmaxf(y, 0.2f * y);
            float e = (mm[q] > 0) ? tf32r(fexp2(y)) : 0.f;
            sm[aoff + (kh + q) * 72 + ia] = e;
        }
        CP_WAIT0();
        __syncthreads();
        if (c + 1 < NCH) {
            const float* src = hb + (size_t)((c + 1) * 32 + kb) * FD + seg * 4;
            uint32_t dst = smb + (KM_B + ((c + 1) & 1) * KM_BSTG + kb * 264 + seg * 4) * 4;
#pragma unroll
            for (int q = 0; q < 8; q++) cp16(dst + q * 128, src + q * 32);
            CP_COMMIT();
            m0 = *(const int4*)(ap + (c + 1) * 32);
            m1 = *(const int4*)(ap + (c + 1) * 32 + 4);
            fa = *(const float4*)(f2p + (c + 1) * 32);
            fb = *(const float4*)(f2p + (c + 1) * 32 + 4);
        }
        const uint32_t* smu = (const uint32_t*)sm;
#pragma unroll
        for (int kf = 0; kf < 4; kf++) {
            const int krow = kf * 8 + (lane & 3);
            uint32_t a[4][4];
#pragma unroll
            for (int mf = 0; mf < 4; mf++) {
                int base = aoff + krow * 72 + mf * 16 + g;
                a[mf][0] = smu[base];
                a[mf][1] = smu[base + 8];
                a[mf][2] = smu[base + 4 * 72];
                a[mf][3] = smu[base + 4 * 72 + 8];
            }
            uint32_t bf[4][2];
#pragma unroll
            for (int nf = 0; nf < 4; nf++) {
                int base = boff + krow * 264 + wn * 32 + nf * 8 + g;
                bf[nf][0] = smu[base];
                bf[nf][1] = smu[base + 4 * 264];
            }
#pragma unroll
            for (int mf = 0; mf < 4; mf++)
#pragma unroll
                for (int nf = 0; nf < 4; nf++)
                    mma_tf32(acc[mf][nf], a[mf], bf[nf]);
        }
    }
    // epilogue: ELU (FMA-pipe) + float2 stores
#pragma unroll
    for (int mf = 0; mf < 4; mf++) {
        const int r0 = i0 + mf * 16 + g;
#pragma unroll
        for (int nf = 0; nf < 4; nf++) {
            const int c0 = wn * 32 + nf * 8 + 2 * (lane & 3);
            float2 p0 = make_float2(felu(acc[mf][nf][0]), felu(acc[mf][nf][1]));
            float2 p1 = make_float2(felu(acc[mf][nf][2]), felu(acc[mf][nf][3]));
            *(float2*)(out + ((size_t)(b * NN + r0)) * FD + c0) = p0;
            *(float2*)(out + ((size_t)(b * NN + r0 + 8)) * FD + c0) = p1;
        }
    }
}

// ---------------------------------------------------------------------------
extern "C" void kernel_launch(void* const* d_in, const int* in_sizes, int n_in,
                              void* d_out, int out_size) {
    const float* input = (const float*)d_in[0];
    const int*   adj   = (const int*)d_in[1];
    const float* W     = (const float*)d_in[2];
    const float* a     = (const float*)d_in[3];
    float* out = (float*)d_out;

    cudaFuncSetAttribute(k_hgen, cudaFuncAttributeMaxDynamicSharedMemorySize, HG_FLOATS * 4);
    cudaFuncSetAttribute(k_att, cudaFuncAttributeMaxDynamicSharedMemorySize, KM_FLOATS * 4);

    k_wa<<<1, 256>>>(W, a);
    k_f12<<<BSZ * NN / 8, 256>>>(input);
    k_Z<<<dim3(NN / 128, 8, BSZ), 128>>>(adj);
    k_hgen<<<BSZ * NN / 64, 256, HG_FLOATS * 4>>>(input, W);
    k_att<<<dim3(NN / 64, BSZ), 256, KM_FLOATS * 4>>>(adj, out);
}

// round 6
// speedup vs baseline: 2.2931x; 1.1106x over previous
#include <cuda_runtime.h>
#include <cuda_fp16.h>
#include <cstdint>
#include <math.h>

#define BSZ 4
#define NN 4096
#define FD 256
#define NCH (NN / 32)
#define LOG2E 1.4426950408889634f

// ---------------- scratch ----------------
__device__ __half g_hnT[BSZ * FD * NN];  // [b][f][j] = h[j,f]/S_j, fp16
__device__ float g_f1[BSZ * NN];         // (X.(W a1)) * log2e
__device__ float g_f2[BSZ * NN];         // (X.(W a2)) * log2e
__device__ float g_c[BSZ * NN];          // lrelu(maxf1 + f2_j)  (log2 units)
__device__ float g_Zp[8][BSZ * NN];      // shifted partial sums
__device__ float g_v[2 * FD];
__device__ float g_mf1[BSZ];

// ---------------- helpers ----------------
__device__ __forceinline__ uint32_t smem_u32(const void* p) {
    uint32_t a;
    asm("{ .reg .u64 t; cvta.to.shared.u64 t, %1; cvt.u32.u64 %0, t; }" : "=r"(a) : "l"(p));
    return a;
}
__device__ __forceinline__ float tf32r(float x) {
    uint32_t r;
    asm("cvt.rna.tf32.f32 %0, %1;" : "=r"(r) : "f"(x));
    return __uint_as_float(r);
}
__device__ __forceinline__ void cp16(uint32_t dst, const void* src) {
    asm volatile("cp.async.cg.shared.global [%0], [%1], 16;" :: "r"(dst), "l"(src));
}
#define CP_COMMIT() asm volatile("cp.async.commit_group;" ::: "memory")
#define CP_WAIT0()  asm volatile("cp.async.wait_group 0;" ::: "memory")

// 2^y on the FMA pipe. |y| < 2^21, rel err ~2e-6.
__device__ __forceinline__ float fexp2(float y) {
    float yr = y + 12582912.0f;
    int n = __float_as_int(yr) - 0x4B400000;
    float r = y - (yr - 12582912.0f);
    float p = fmaf(0.0013333558f, r, 0.0096181291f);
    p = fmaf(p, r, 0.0555041086f);
    p = fmaf(p, r, 0.2402265069f);
    p = fmaf(p, r, 0.6931471806f);
    p = fmaf(p, r, 1.0f);
    return __int_as_float(__float_as_int(p) + (n << 23));
}
__device__ __forceinline__ float felu(float x) {
    float q = fmaf(0.0083333338f, x, 0.0416666679f);
    q = fmaf(q, x, 0.16666667f);
    q = fmaf(q, x, 0.5f);
    q = fmaf(q, x, 1.0f);
    float small = x * q;
    float big = fexp2(x * LOG2E) - 1.0f;
    float neg = (x >= -0.25f) ? small : big;
    return (x > 0.f) ? x : neg;
}
__device__ __forceinline__ void ldsm4(uint32_t* r, uint32_t addr) {
    asm volatile("ldmatrix.sync.aligned.m8n8.x4.shared.b16 {%0,%1,%2,%3}, [%4];"
                 : "=r"(r[0]), "=r"(r[1]), "=r"(r[2]), "=r"(r[3]) : "r"(addr));
}
__device__ __forceinline__ void mma_f16(float* d, const uint32_t* a, const uint32_t* b2) {
    asm volatile(
        "mma.sync.aligned.m16n8k16.row.col.f32.f16.f16.f32 "
        "{%0,%1,%2,%3}, {%4,%5,%6,%7}, {%8,%9}, {%0,%1,%2,%3};"
        : "+f"(d[0]), "+f"(d[1]), "+f"(d[2]), "+f"(d[3])
        : "r"(a[0]), "r"(a[1]), "r"(a[2]), "r"(a[3]), "r"(b2[0]), "r"(b2[1]));
}
__device__ __forceinline__ void mma_tf32(float* d, const uint32_t* a, const uint32_t* bb) {
    asm volatile(
        "mma.sync.aligned.m16n8k8.row.col.f32.tf32.tf32.f32 "
        "{%0,%1,%2,%3}, {%4,%5,%6,%7}, {%8,%9}, {%0,%1,%2,%3};"
        : "+f"(d[0]), "+f"(d[1]), "+f"(d[2]), "+f"(d[3])
        : "r"(a[0]), "r"(a[1]), "r"(a[2]), "r"(a[3]), "r"(bb[0]), "r"(bb[1]));
}

// ---------------------------------------------------------------------------
// K0: v = (W @ a) * log2e
// ---------------------------------------------------------------------------
__global__ __launch_bounds__(256) void k_wa(const float* __restrict__ W,
                                            const float* __restrict__ a) {
    const int w = threadIdx.x >> 5, lane = threadIdx.x & 31;
    for (int r = w; r < FD; r += 8) {
        float s1 = 0.f, s2 = 0.f;
        for (int f = lane; f < FD; f += 32) {
            float wv = W[r * FD + f];
            s1 = fmaf(wv, a[f], s1);
            s2 = fmaf(wv, a[FD + f], s2);
        }
#pragma unroll
        for (int o = 16; o; o >>= 1) {
            s1 += __shfl_xor_sync(~0u, s1, o);
            s2 += __shfl_xor_sync(~0u, s2, o);
        }
        if (lane == 0) { g_v[r] = s1 * LOG2E; g_v[FD + r] = s2 * LOG2E; }
    }
}

// ---------------------------------------------------------------------------
// K1: f1 = X.v1, f2 = X.v2
// ---------------------------------------------------------------------------
__global__ __launch_bounds__(256) void k_f12(const float* __restrict__ X) {
    const int row = blockIdx.x * 8 + (threadIdx.x >> 5);
    const int lane = threadIdx.x & 31;
    const float* xr = X + (size_t)row * FD;
    float s1 = 0.f, s2 = 0.f;
#pragma unroll
    for (int k = lane; k < FD; k += 32) {
        float xv = xr[k];
        s1 = fmaf(xv, g_v[k], s1);
        s2 = fmaf(xv, g_v[FD + k], s2);
    }
#pragma unroll
    for (int o = 16; o; o >>= 1) {
        s1 += __shfl_xor_sync(~0u, s1, o);
        s2 += __shfl_xor_sync(~0u, s2, o);
    }
    if (lane == 0) { g_f1[row] = s1; g_f2[row] = s2; }
}

// K1b: per-batch max of f1
__global__ __launch_bounds__(256) void k_max() {
    __shared__ float red[256];
    const int b = blockIdx.x;
    float m = -1e30f;
    for (int i = threadIdx.x; i < NN; i += 256)
        m = fmaxf(m, g_f1[b * NN + i]);
    red[threadIdx.x] = m;
    __syncthreads();
    for (int o = 128; o; o >>= 1) {
        if (threadIdx.x < o) red[threadIdx.x] = fmaxf(red[threadIdx.x], red[threadIdx.x + o]);
        __syncthreads();
    }
    if (threadIdx.x == 0) g_mf1[b] = red[0];
}
// K1c: c_j = lrelu(maxf1 + f2_j)
__global__ __launch_bounds__(256) void k_c() {
    const int idx = blockIdx.x * 256 + threadIdx.x;
    const int b = idx >> 12;
    float s = g_mf1[b] + g_f2[idx];
    g_c[idx] = fmaxf(s, 0.2f * s);
}

// ---------------------------------------------------------------------------
// K2: shifted partial sums  S_j = sum_i adj * 2^(lrelu(f1+f2) - c_j)
// ---------------------------------------------------------------------------
__global__ __launch_bounds__(128) void k_Z(const int* __restrict__ adj) {
    const int b = blockIdx.z;
    const int j = blockIdx.x * 128 + threadIdx.x;
    const int split = blockIdx.y;
    const int ilen = NN / 8;
    const int i0 = split * ilen;
    const float f2j = g_f2[b * NN + j];
    const float cj = g_c[b * NN + j];
    const int* ap = adj + ((size_t)b * NN + i0) * NN + j;
    const float* f1p = g_f1 + b * NN + i0;
    float acc = 0.f;
#pragma unroll 8
    for (int i = 0; i < ilen; i++) {
        int m = ap[(size_t)i * NN];
        float y = f1p[i] + f2j;
        y = fmaxf(y, 0.2f * y) - cj;
        float e = fexp2(y);
        acc += (m > 0) ? e : 0.f;
    }
    g_Zp[split][b * NN + j] = acc;
}

// ---------------------------------------------------------------------------
// K3: hnT[b][f][j] = fp16( (X@W)[j,f] / S_j )  via tf32 mma + smem transpose
// ---------------------------------------------------------------------------
#define HG_ZI 0
#define HG_A 64
#define HG_ASTG (32 * 72)
#define HG_B (64 + 2 * HG_ASTG)
#define HG_BSTG (32 * 264)
#define HG_FLOATS (HG_B + 2 * HG_BSTG)
__global__ void __launch_bounds__(256, 2) k_hgen(const float* __restrict__ X,
                                                 const float* __restrict__ W) {
    extern __shared__ float sm[];
    const uint32_t smb = smem_u32(sm);
    const int t = threadIdx.x, lane = t & 31, wn = t >> 5, g = lane >> 2;
    const int R0 = blockIdx.x * 64;
    const int ia = t & 63, kh = (t >> 6) * 8;
    const int kb = t >> 3, seg = t & 7;

    if (t < 64) {
        float z = 0.f;
#pragma unroll
        for (int s = 0; s < 8; s++) z += g_Zp[s][R0 + t];
        sm[HG_ZI + t] = 1.0f / z;
    }

    const float* xrow = X + (size_t)(R0 + ia) * FD + kh;
    {
        const float* src = W + (size_t)kb * FD + seg * 4;
        uint32_t dst = smb + (HG_B + kb * 264 + seg * 4) * 4;
#pragma unroll
        for (int q = 0; q < 8; q++) cp16(dst + q * 128, src + q * 32);
        CP_COMMIT();
    }

    float acc[4][4][4] = {};
    for (int c = 0; c < 8; c++) {
        const int aoff = HG_A + (c & 1) * HG_ASTG;
        const int boff = HG_B + (c & 1) * HG_BSTG;
        float4 x0 = *(const float4*)(xrow + c * 32);
        float4 x1 = *(const float4*)(xrow + c * 32 + 4);
        float e[8] = {x0.x, x0.y, x0.z, x0.w, x1.x, x1.y, x1.z, x1.w};
#pragma unroll
        for (int q = 0; q < 8; q++)
            sm[aoff + (kh + q) * 72 + ia] = tf32r(e[q]);
        CP_WAIT0();
        __syncthreads();
        if (c < 7) {
            const float* src = W + (size_t)((c + 1) * 32 + kb) * FD + seg * 4;
            uint32_t dst = smb + (HG_B + ((c + 1) & 1) * HG_BSTG + kb * 264 + seg * 4) * 4;
#pragma unroll
            for (int q = 0; q < 8; q++) cp16(dst + q * 128, src + q * 32);
            CP_COMMIT();
        }
        const uint32_t* smu = (const uint32_t*)sm;
#pragma unroll
        for (int kf = 0; kf < 4; kf++) {
            const int krow = kf * 8 + (lane & 3);
            uint32_t a[4][4];
#pragma unroll
            for (int mf = 0; mf < 4; mf++) {
                int base = aoff + krow * 72 + mf * 16 + g;
                a[mf][0] = smu[base];
                a[mf][1] = smu[base + 8];
                a[mf][2] = smu[base + 4 * 72];
                a[mf][3] = smu[base + 4 * 72 + 8];
            }
            uint32_t bf[4][2];
#pragma unroll
            for (int nf = 0; nf < 4; nf++) {
                int base = boff + krow * 264 + wn * 32 + nf * 8 + g;
                bf[nf][0] = smu[base];
                bf[nf][1] = smu[base + 4 * 264];
            }
#pragma unroll
            for (int mf = 0; mf < 4; mf++)
#pragma unroll
                for (int nf = 0; nf < 4; nf++)
                    mma_tf32(acc[mf][nf], a[mf], bf[nf]);
        }
    }

    // epilogue: scale by 1/S, fp16, transpose via smem, coalesced STG
    __syncthreads();
    __half* Ts = (__half*)(sm + HG_B);           // [f=256][j=64], stride 72 halves
#pragma unroll
    for (int mf = 0; mf < 4; mf++) {
        const int r0 = mf * 16 + g;
        const float zi0 = sm[HG_ZI + r0], zi1 = sm[HG_ZI + r0 + 8];
#pragma unroll
        for (int nf = 0; nf < 4; nf++) {
            const int c0 = wn * 32 + nf * 8 + 2 * (lane & 3);
            Ts[(c0)     * 72 + r0]     = __float2half_rn(acc[mf][nf][0] * zi0);
            Ts[(c0 + 1) * 72 + r0]     = __float2half_rn(acc[mf][nf][1] * zi0);
            Ts[(c0)     * 72 + r0 + 8] = __float2half_rn(acc[mf][nf][2] * zi1);
            Ts[(c0 + 1) * 72 + r0 + 8] = __float2half_rn(acc[mf][nf][3] * zi1);
        }
    }
    __syncthreads();
    const int b = R0 >> 12, jloc = R0 & (NN - 1);
    __half* dst = g_hnT + ((size_t)b * FD + t) * NN + jloc;
    const uint4* srcv = (const uint4*)(Ts + t * 72);
#pragma unroll
    for (int q = 0; q < 8; q++)          // FIX: 64 halves (8 x uint4), was 4
        ((uint4*)dst)[q] = srcv[q];
}

// ---------------------------------------------------------------------------
// K4: out = elu( E' @ B' ) via fp16 mma m16n8k16 + ldmatrix
//   CTA 128(i) x 256(f), 256 thr, warp tile 64x64 (wm 0..1, wn 0..3)
// ---------------------------------------------------------------------------
#define AT_STR 40                       // row stride in halves
#define AT_ASTG (128 * AT_STR)          // 5120 halves per A stage
#define AT_B0 (2 * AT_ASTG)             // 10240
#define AT_BSTG (256 * AT_STR)          // 10240 halves per B stage
#define AT_HALVES (AT_B0 + 2 * AT_BSTG) // 30720
__global__ void __launch_bounds__(256, 1) k_att(const int* __restrict__ adj,
                                                float* __restrict__ out) {
    extern __shared__ __half sh[];
    const uint32_t smb = smem_u32(sh);
    const int t = threadIdx.x, lane = t & 31, wid = t >> 5;
    const int wm = wid >> 2, wn = wid & 3;
    const int g = lane >> 2, c2 = lane & 3;
    const int b = blockIdx.y;
    const int i0 = blockIdx.x * 128;

    // builder roles
    const int ia = t & 127;
    const int kh = (t >> 7) * 16;
    const int* ap = adj + ((size_t)(b * NN + i0 + ia)) * NN + kh;
    const float* f2p = g_f2 + b * NN + kh;
    const float* cjp = g_c + b * NN + kh;
    const float f1v = g_f1[b * NN + i0 + ia];
    const __half* hT = g_hnT + (size_t)b * FD * NN;

    // ldmatrix lane bases (bytes, stage-relative)
    const uint32_t aBase = smb + (uint32_t)((wm * 64 + (lane & 15)) * AT_STR + (lane >> 4) * 8) * 2;
    const uint32_t bBase = smb + (uint32_t)((wn * 64 + (lane & 7) + (lane >> 4) * 8) * AT_STR
                                            + ((lane >> 3) & 1) * 8) * 2;

    // prefetch B(0): thread t owns f-row t
    {
        const __half* src = hT + (size_t)t * NN;
        uint32_t dst = smb + (AT_B0 + t * AT_STR) * 2;
#pragma unroll
        for (int seg = 0; seg < 4; seg++) cp16(dst + seg * 16, src + seg * 8);
        CP_COMMIT();
    }
    int4 m[4];
#pragma unroll
    for (int q = 0; q < 4; q++) m[q] = ((const int4*)ap)[q];

    float acc[4][8][4] = {};

    for (int c = 0; c < NCH; c++) {
        const int j0 = c * 32;

        // ---- build A(c): fp16 shifted exp weights ----
        int mm[16] = {m[0].x, m[0].y, m[0].z, m[0].w, m[1].x, m[1].y, m[1].z, m[1].w,
                      m[2].x, m[2].y, m[2].z, m[2].w, m[3].x, m[3].y, m[3].z, m[3].w};
        float ev[16];
#pragma unroll
        for (int q4 = 0; q4 < 4; q4++) {
            float4 F2 = *(const float4*)(f2p + j0 + q4 * 4);
            float4 CJ = *(const float4*)(cjp + j0 + q4 * 4);
            float fv[4] = {F2.x, F2.y, F2.z, F2.w};
            float cv[4] = {CJ.x, CJ.y, CJ.z, CJ.w};
#pragma unroll
            for (int r = 0; r < 4; r++) {
                float s = f1v + fv[r];
                float y = fmaxf(s, 0.2f * s) - cv[r];
                ev[q4 * 4 + r] = (mm[q4 * 4 + r] > 0) ? fexp2(y) : 0.f;
            }
        }
        __half2 h2[8];
#pragma unroll
        for (int p = 0; p < 8; p++) h2[p] = __floats2half2_rn(ev[2 * p], ev[2 * p + 1]);
        {
            __half* sA = sh + (c & 1) * AT_ASTG + ia * AT_STR + kh;
            *(uint4*)(sA) = *(uint4*)(&h2[0]);
            *(uint4*)(sA + 8) = *(uint4*)(&h2[4]);
        }

        CP_WAIT0();
        __syncthreads();

        // ---- prefetch B(c+1) + adj(c+1) ----
        if (c + 1 < NCH) {
            const __half* src = hT + (size_t)t * NN + (c + 1) * 32;
            uint32_t dst = smb + (AT_B0 + ((c + 1) & 1) * AT_BSTG + t * AT_STR) * 2;
#pragma unroll
            for (int seg = 0; seg < 4; seg++) cp16(dst + seg * 16, src + seg * 8);
            CP_COMMIT();
#pragma unroll
            for (int q = 0; q < 4; q++)
                m[q] = *(const int4*)(ap + (c + 1) * 32 + q * 4);
        }

        // ---- mma ----
        const uint32_t aS = aBase + (c & 1) * (AT_ASTG * 2);
        const uint32_t bS = bBase + (AT_B0 + (c & 1) * AT_BSTG) * 2;
#pragma unroll
        for (int kf = 0; kf < 2; kf++) {
            uint32_t af[4][4];
#pragma unroll
            for (int mf = 0; mf < 4; mf++)
                ldsm4(af[mf], aS + mf * (16 * AT_STR * 2) + kf * 32);
            uint32_t bf[4][4];
#pragma unroll
            for (int nfp = 0; nfp < 4; nfp++)
                ldsm4(bf[nfp], bS + nfp * (16 * AT_STR * 2) + kf * 32);
#pragma unroll
            for (int mf = 0; mf < 4; mf++)
#pragma unroll
                for (int nf = 0; nf < 8; nf++)
                    mma_f16(acc[mf][nf], af[mf], &bf[nf >> 1][(nf & 1) * 2]);
        }
    }

    // ---- epilogue ----
#pragma unroll
    for (int mf = 0; mf < 4; mf++) {
        const int r = i0 + wm * 64 + mf * 16 + g;
#pragma unroll
        for (int nf = 0; nf < 8; nf++) {
            const int col = wn * 64 + nf * 8 + 2 * c2;
            float2 p0 = make_float2(felu(acc[mf][nf][0]), felu(acc[mf][nf][1]));
            float2 p1 = make_float2(felu(acc[mf][nf][2]), felu(acc[mf][nf][3]));
            *(float2*)(out + ((size_t)(b * NN + r)) * FD + col) = p0;
            *(float2*)(out + ((size_t)(b * NN + r + 8)) * FD + col) = p1;
        }
    }
}

// ---------------------------------------------------------------------------
extern "C" void kernel_launch(void* const* d_in, const int* in_sizes, int n_in,
                              void* d_out, int out_size) {
    const float* input = (const float*)d_in[0];
    const int*   adj   = (const int*)d_in[1];
    const float* W     = (const float*)d_in[2];
    const float* a     = (const float*)d_in[3];
    float* out = (float*)d_out;

    cudaFuncSetAttribute(k_hgen, cudaFuncAttributeMaxDynamicSharedMemorySize, HG_FLOATS * 4);
    cudaFuncSetAttribute(k_att, cudaFuncAttributeMaxDynamicSharedMemorySize, AT_HALVES * 2);

    k_wa<<<1, 256>>>(W, a);
    k_f12<<<BSZ * NN / 8, 256>>>(input);
    k_max<<<BSZ, 256>>>();
    k_c<<<BSZ * NN / 256, 256>>>();
    k_Z<<<dim3(NN / 128, 8, BSZ), 128>>>(adj);
    k_hgen<<<BSZ * NN / 64, 256, HG_FLOATS * 4>>>(input, W);
    k_att<<<dim3(NN / 128, BSZ), 256, AT_HALVES * 2>>>(adj, out);
}

// round 7
// speedup vs baseline: 2.5264x; 1.1018x over previous
#include <cuda_runtime.h>
#include <cuda_fp16.h>
#include <cstdint>
#include <math.h>

#define BSZ 4
#define NN 4096
#define FD 256
#define NCH (NN / 32)
#define LOG2E 1.4426950408889634f

// ---------------- scratch ----------------
__device__ __half g_hnT[BSZ * FD * NN];  // [b][f][j] = h[j,f]/S_j, fp16
__device__ float g_f1[BSZ * NN];
__device__ float g_f2[BSZ * NN];
__device__ float g_c[BSZ * NN];          // lrelu(maxf1 + f2_j), log2 units
__device__ float g_Zp[8][BSZ * NN];
__device__ float g_v[2 * FD];

// ---------------- helpers ----------------
__device__ __forceinline__ uint32_t smem_u32(const void* p) {
    uint32_t a;
    asm("{ .reg .u64 t; cvta.to.shared.u64 t, %1; cvt.u32.u64 %0, t; }" : "=r"(a) : "l"(p));
    return a;
}
__device__ __forceinline__ float tf32r(float x) {
    uint32_t r;
    asm("cvt.rna.tf32.f32 %0, %1;" : "=r"(r) : "f"(x));
    return __uint_as_float(r);
}
__device__ __forceinline__ void cp16(uint32_t dst, const void* src) {
    asm volatile("cp.async.cg.shared.global [%0], [%1], 16;" :: "r"(dst), "l"(src));
}
#define CP_COMMIT() asm volatile("cp.async.commit_group;" ::: "memory")
#define CP_WAIT0()  asm volatile("cp.async.wait_group 0;" ::: "memory")

// 2^y on the FMA pipe. rel err ~2e-6.
__device__ __forceinline__ float fexp2(float y) {
    float yr = y + 12582912.0f;
    int n = __float_as_int(yr) - 0x4B400000;
    float r = y - (yr - 12582912.0f);
    float p = fmaf(0.0013333558f, r, 0.0096181291f);
    p = fmaf(p, r, 0.0555041086f);
    p = fmaf(p, r, 0.2402265069f);
    p = fmaf(p, r, 0.6931471806f);
    p = fmaf(p, r, 1.0f);
    return __int_as_float(__float_as_int(p) + (n << 23));
}
__device__ __forceinline__ float felu(float x) {
    float q = fmaf(0.0083333338f, x, 0.0416666679f);
    q = fmaf(q, x, 0.16666667f);
    q = fmaf(q, x, 0.5f);
    q = fmaf(q, x, 1.0f);
    float small = x * q;
    float big = fexp2(x * LOG2E) - 1.0f;
    float neg = (x >= -0.25f) ? small : big;
    return (x > 0.f) ? x : neg;
}
__device__ __forceinline__ void ldsm4(uint32_t* r, uint32_t addr) {
    asm volatile("ldmatrix.sync.aligned.m8n8.x4.shared.b16 {%0,%1,%2,%3}, [%4];"
                 : "=r"(r[0]), "=r"(r[1]), "=r"(r[2]), "=r"(r[3]) : "r"(addr));
}
__device__ __forceinline__ void mma_f16(float* d, const uint32_t* a, const uint32_t* b2) {
    asm volatile(
        "mma.sync.aligned.m16n8k16.row.col.f32.f16.f16.f32 "
        "{%0,%1,%2,%3}, {%4,%5,%6,%7}, {%8,%9}, {%0,%1,%2,%3};"
        : "+f"(d[0]), "+f"(d[1]), "+f"(d[2]), "+f"(d[3])
        : "r"(a[0]), "r"(a[1]), "r"(a[2]), "r"(a[3]), "r"(b2[0]), "r"(b2[1]));
}
__device__ __forceinline__ void mma_tf32(float* d, const uint32_t* a, const uint32_t* bb) {
    asm volatile(
        "mma.sync.aligned.m16n8k8.row.col.f32.tf32.tf32.f32 "
        "{%0,%1,%2,%3}, {%4,%5,%6,%7}, {%8,%9}, {%0,%1,%2,%3};"
        : "+f"(d[0]), "+f"(d[1]), "+f"(d[2]), "+f"(d[3])
        : "r"(a[0]), "r"(a[1]), "r"(a[2]), "r"(a[3]), "r"(bb[0]), "r"(bb[1]));
}

// ---------------------------------------------------------------------------
// K0: v = (W @ a) * log2e
// ---------------------------------------------------------------------------
__global__ __launch_bounds__(256) void k_wa(const float* __restrict__ W,
                                            const float* __restrict__ a) {
    const int w = threadIdx.x >> 5, lane = threadIdx.x & 31;
    for (int r = w; r < FD; r += 8) {
        float s1 = 0.f, s2 = 0.f;
        for (int f = lane; f < FD; f += 32) {
            float wv = W[r * FD + f];
            s1 = fmaf(wv, a[f], s1);
            s2 = fmaf(wv, a[FD + f], s2);
        }
#pragma unroll
        for (int o = 16; o; o >>= 1) {
            s1 += __shfl_xor_sync(~0u, s1, o);
            s2 += __shfl_xor_sync(~0u, s2, o);
        }
        if (lane == 0) { g_v[r] = s1 * LOG2E; g_v[FD + r] = s2 * LOG2E; }
    }
}

// ---------------------------------------------------------------------------
// K1: f1 = X.v1, f2 = X.v2
// ---------------------------------------------------------------------------
__global__ __launch_bounds__(256) void k_f12(const float* __restrict__ X) {
    const int row = blockIdx.x * 8 + (threadIdx.x >> 5);
    const int lane = threadIdx.x & 31;
    const float* xr = X + (size_t)row * FD;
    float s1 = 0.f, s2 = 0.f;
#pragma unroll
    for (int k = lane; k < FD; k += 32) {
        float xv = xr[k];
        s1 = fmaf(xv, g_v[k], s1);
        s2 = fmaf(xv, g_v[FD + k], s2);
    }
#pragma unroll
    for (int o = 16; o; o >>= 1) {
        s1 += __shfl_xor_sync(~0u, s1, o);
        s2 += __shfl_xor_sync(~0u, s2, o);
    }
    if (lane == 0) { g_f1[row] = s1; g_f2[row] = s2; }
}

// ---------------------------------------------------------------------------
// K1b: merged per-batch max(f1) + c_j = lrelu(maxf1 + f2_j)
// ---------------------------------------------------------------------------
__global__ __launch_bounds__(256) void k_maxc() {
    __shared__ float red[256];
    const int b = blockIdx.x;
    const int tid = threadIdx.x;
    float m = -1e30f;
    for (int i = tid; i < NN; i += 256)
        m = fmaxf(m, g_f1[b * NN + i]);
    red[tid] = m;
    __syncthreads();
    for (int o = 128; o; o >>= 1) {
        if (tid < o) red[tid] = fmaxf(red[tid], red[tid + o]);
        __syncthreads();
    }
    const float mf = red[0];
    for (int j = tid; j < NN; j += 256) {
        float s = mf + g_f2[b * NN + j];
        g_c[b * NN + j] = fmaxf(s, 0.2f * s);
    }
}

// ---------------------------------------------------------------------------
// K2: shifted partial sums  S_j = sum_i adj * 2^(lrelu(f1+f2) - c_j)
// ---------------------------------------------------------------------------
__global__ __launch_bounds__(128) void k_Z(const int* __restrict__ adj) {
    const int b = blockIdx.z;
    const int j = blockIdx.x * 128 + threadIdx.x;
    const int split = blockIdx.y;
    const int ilen = NN / 8;
    const int i0 = split * ilen;
    const float f2j = g_f2[b * NN + j];
    const float cj = g_c[b * NN + j];
    const int* ap = adj + ((size_t)b * NN + i0) * NN + j;
    const float* f1p = g_f1 + b * NN + i0;
    float acc = 0.f;
#pragma unroll 8
    for (int i = 0; i < ilen; i++) {
        int m = ap[(size_t)i * NN];
        float y = f1p[i] + f2j;
        y = fmaxf(y, 0.2f * y) - cj;
        float e = fexp2(y);
        acc += (m > 0) ? e : 0.f;
    }
    g_Zp[split][b * NN + j] = acc;
}

// ---------------------------------------------------------------------------
// K3: hnT[b][f][j] = fp16( (X@W)[j,f] / S_j )  via tf32 mma + smem transpose
// ---------------------------------------------------------------------------
#define HG_ZI 0
#define HG_A 64
#define HG_ASTG (32 * 72)
#define HG_B (64 + 2 * HG_ASTG)
#define HG_BSTG (32 * 264)
#define HG_FLOATS (HG_B + 2 * HG_BSTG)
__global__ void __launch_bounds__(256, 2) k_hgen(const float* __restrict__ X,
                                                 const float* __restrict__ W) {
    extern __shared__ float sm[];
    const uint32_t smb = smem_u32(sm);
    const int t = threadIdx.x, lane = t & 31, wn = t >> 5, g = lane >> 2;
    const int R0 = blockIdx.x * 64;
    const int ia = t & 63, kh = (t >> 6) * 8;
    const int kb = t >> 3, seg = t & 7;

    if (t < 64) {
        float z = 0.f;
#pragma unroll
        for (int s = 0; s < 8; s++) z += g_Zp[s][R0 + t];
        sm[HG_ZI + t] = 1.0f / z;
    }

    const float* xrow = X + (size_t)(R0 + ia) * FD + kh;
    {
        const float* src = W + (size_t)kb * FD + seg * 4;
        uint32_t dst = smb + (HG_B + kb * 264 + seg * 4) * 4;
#pragma unroll
        for (int q = 0; q < 8; q++) cp16(dst + q * 128, src + q * 32);
        CP_COMMIT();
    }

    float acc[4][4][4] = {};
    for (int c = 0; c < 8; c++) {
        const int aoff = HG_A + (c & 1) * HG_ASTG;
        const int boff = HG_B + (c & 1) * HG_BSTG;
        float4 x0 = *(const float4*)(xrow + c * 32);
        float4 x1 = *(const float4*)(xrow + c * 32 + 4);
        float e[8] = {x0.x, x0.y, x0.z, x0.w, x1.x, x1.y, x1.z, x1.w};
#pragma unroll
        for (int q = 0; q < 8; q++)
            sm[aoff + (kh + q) * 72 + ia] = tf32r(e[q]);
        CP_WAIT0();
        __syncthreads();
        if (c < 7) {
            const float* src = W + (size_t)((c + 1) * 32 + kb) * FD + seg * 4;
            uint32_t dst = smb + (HG_B + ((c + 1) & 1) * HG_BSTG + kb * 264 + seg * 4) * 4;
#pragma unroll
            for (int q = 0; q < 8; q++) cp16(dst + q * 128, src + q * 32);
            CP_COMMIT();
        }
        const uint32_t* smu = (const uint32_t*)sm;
#pragma unroll
        for (int kf = 0; kf < 4; kf++) {
            const int krow = kf * 8 + (lane & 3);
            uint32_t a[4][4];
#pragma unroll
            for (int mf = 0; mf < 4; mf++) {
                int base = aoff + krow * 72 + mf * 16 + g;
                a[mf][0] = smu[base];
                a[mf][1] = smu[base + 8];
                a[mf][2] = smu[base + 4 * 72];
                a[mf][3] = smu[base + 4 * 72 + 8];
            }
            uint32_t bf[4][2];
#pragma unroll
            for (int nf = 0; nf < 4; nf++) {
                int base = boff + krow * 264 + wn * 32 + nf * 8 + g;
                bf[nf][0] = smu[base];
                bf[nf][1] = smu[base + 4 * 264];
            }
#pragma unroll
            for (int mf = 0; mf < 4; mf++)
#pragma unroll
                for (int nf = 0; nf < 4; nf++)
                    mma_tf32(acc[mf][nf], a[mf], bf[nf]);
        }
    }

    __syncthreads();
    __half* Ts = (__half*)(sm + HG_B);           // [f=256][j=64], stride 72 halves
#pragma unroll
    for (int mf = 0; mf < 4; mf++) {
        const int r0 = mf * 16 + g;
        const float zi0 = sm[HG_ZI + r0], zi1 = sm[HG_ZI + r0 + 8];
#pragma unroll
        for (int nf = 0; nf < 4; nf++) {
            const int c0 = wn * 32 + nf * 8 + 2 * (lane & 3);
            Ts[(c0)     * 72 + r0]     = __float2half_rn(acc[mf][nf][0] * zi0);
            Ts[(c0 + 1) * 72 + r0]     = __float2half_rn(acc[mf][nf][1] * zi0);
            Ts[(c0)     * 72 + r0 + 8] = __float2half_rn(acc[mf][nf][2] * zi1);
            Ts[(c0 + 1) * 72 + r0 + 8] = __float2half_rn(acc[mf][nf][3] * zi1);
        }
    }
    __syncthreads();
    const int b = R0 >> 12, jloc = R0 & (NN - 1);
    __half* dst = g_hnT + ((size_t)b * FD + t) * NN + jloc;
    const uint4* srcv = (const uint4*)(Ts + t * 72);
#pragma unroll
    for (int q = 0; q < 8; q++)
        ((uint4*)dst)[q] = srcv[q];
}

// ---------------------------------------------------------------------------
// K4: out = elu( E' @ B' )  fp16 mma, 512 threads, overlapped A-build.
//   CTA 128(i) x 256(f); 16 warps (wm 0..3, wn 0..3), warp tile 32x64.
// ---------------------------------------------------------------------------
#define AT_STR 40
#define AT_ASTG (128 * AT_STR)          // 5120 halves per A stage
#define AT_B0 (2 * AT_ASTG)             // 10240
#define AT_BSTG (256 * AT_STR)          // 10240 halves per B stage
#define AT_HALVES (AT_B0 + 2 * AT_BSTG) // 30720 (60 KB)
__global__ void __launch_bounds__(512, 1) k_att(const int* __restrict__ adj,
                                                float* __restrict__ out) {
    extern __shared__ __half sh[];
    const uint32_t smb = smem_u32(sh);
    const int t = threadIdx.x, lane = t & 31, wid = t >> 5;
    const int wm = wid >> 2, wn = wid & 3;
    const int g = lane >> 2, c2 = lane & 3;
    const int b = blockIdx.y;
    const int i0 = blockIdx.x * 128;

    // A-builder roles: each thread builds 8 halves of one row
    const int ia = t & 127;
    const int kh = (t >> 7) * 8;                 // 0,8,16,24
    const int* ap = adj + ((size_t)(b * NN + i0 + ia)) * NN + kh;
    const float* f2p = g_f2 + b * NN + kh;
    const float* cjp = g_c + b * NN + kh;
    const float f1v = g_f1[b * NN + i0 + ia];
    const __half* hT = g_hnT + (size_t)b * FD * NN;

    // B-loader roles: thread pair covers one f-row (32 halves = 64B)
    const int fr = t >> 1, sg = t & 1;

    // ldmatrix lane bases
    const uint32_t aBase = smb + (uint32_t)((wm * 32 + (lane & 15)) * AT_STR + (lane >> 4) * 8) * 2;
    const uint32_t bBase = smb + (uint32_t)((wn * 64 + (lane & 7) + (lane >> 4) * 8) * AT_STR
                                            + ((lane >> 3) & 1) * 8) * 2;

    // ---- prologue: B(0) prefetch, adj(0), build A(0) ----
    {
        const __half* src = hT + (size_t)fr * NN + sg * 16;
        uint32_t dst = smb + (AT_B0 + fr * AT_STR) * 2 + sg * 32;
        cp16(dst, src);
        cp16(dst + 16, src + 8);
        CP_COMMIT();
    }
    int4 m0 = ((const int4*)ap)[0];
    int4 m1 = ((const int4*)ap)[1];
    {
        int mm[8] = {m0.x, m0.y, m0.z, m0.w, m1.x, m1.y, m1.z, m1.w};
        float ev[8];
#pragma unroll
        for (int r = 0; r < 8; r++) {
            float s = f1v + f2p[r];
            float y = fmaxf(s, 0.2f * s) - cjp[r];
            ev[r] = (mm[r] > 0) ? fexp2(y) : 0.f;
        }
        __half2 h2[4];
#pragma unroll
        for (int p = 0; p < 4; p++) h2[p] = __floats2half2_rn(ev[2 * p], ev[2 * p + 1]);
        *(uint4*)(sh + ia * AT_STR + kh) = *(uint4*)h2;
    }
    CP_WAIT0();
    __syncthreads();

    float acc[2][8][4] = {};

    for (int c = 0; c < NCH; c++) {
        // ---- issue next-chunk loads first (overlap with mma) ----
        if (c + 1 < NCH) {
            const __half* src = hT + (size_t)fr * NN + (c + 1) * 32 + sg * 16;
            uint32_t dst = smb + (AT_B0 + ((c + 1) & 1) * AT_BSTG + fr * AT_STR) * 2 + sg * 32;
            cp16(dst, src);
            cp16(dst + 16, src + 8);
            CP_COMMIT();
            m0 = *(const int4*)(ap + (c + 1) * 32);
            m1 = *(const int4*)(ap + (c + 1) * 32 + 4);
        }

        // ---- mma(c) ----
        const uint32_t aS = aBase + (c & 1) * (AT_ASTG * 2);
        const uint32_t bS = bBase + ((c & 1) * AT_BSTG) * 2 + AT_B0 * 2;
#pragma unroll
        for (int kf = 0; kf < 2; kf++) {
            uint32_t af[2][4];
#pragma unroll
            for (int mf = 0; mf < 2; mf++)
                ldsm4(af[mf], aS + mf * (16 * AT_STR * 2) + kf * 32);
            uint32_t bf[4][4];
#pragma unroll
            for (int nfp = 0; nfp < 4; nfp++)
                ldsm4(bf[nfp], bS + nfp * (16 * AT_STR * 2) + kf * 32);
#pragma unroll
            for (int mf = 0; mf < 2; mf++)
#pragma unroll
                for (int nf = 0; nf < 8; nf++)
                    mma_f16(acc[mf][nf], af[mf], &bf[nf >> 1][(nf & 1) * 2]);
        }

        // ---- build A(c+1) (FMA pipe; overlaps tensor pipe) ----
        if (c + 1 < NCH) {
            const int j1 = (c + 1) * 32;
            int mm[8] = {m0.x, m0.y, m0.z, m0.w, m1.x, m1.y, m1.z, m1.w};
            float ev[8];
#pragma unroll
            for (int r = 0; r < 8; r++) {
                float s = f1v + f2p[j1 + r];
                float y = fmaxf(s, 0.2f * s) - cjp[j1 + r];
                ev[r] = (mm[r] > 0) ? fexp2(y) : 0.f;
            }
            __half2 h2[4];
#pragma unroll
            for (int p = 0; p < 4; p++) h2[p] = __floats2half2_rn(ev[2 * p], ev[2 * p + 1]);
            *(uint4*)(sh + ((c + 1) & 1) * AT_ASTG + ia * AT_STR + kh) = *(uint4*)h2;

            CP_WAIT0();
            __syncthreads();
        }
    }

    // ---- epilogue ----
#pragma unroll
    for (int mf = 0; mf < 2; mf++) {
        const int r = i0 + wm * 32 + mf * 16 + g;
#pragma unroll
        for (int nf = 0; nf < 8; nf++) {
            const int col = wn * 64 + nf * 8 + 2 * c2;
            float2 p0 = make_float2(felu(acc[mf][nf][0]), felu(acc[mf][nf][1]));
            float2 p1 = make_float2(felu(acc[mf][nf][2]), felu(acc[mf][nf][3]));
            *(float2*)(out + ((size_t)(b * NN + r)) * FD + col) = p0;
            *(float2*)(out + ((size_t)(b * NN + r + 8)) * FD + col) = p1;
        }
    }
}

// ---------------------------------------------------------------------------
extern "C" void kernel_launch(void* const* d_in, const int* in_sizes, int n_in,
                              void* d_out, int out_size) {
    const float* input = (const float*)d_in[0];
    const int*   adj   = (const int*)d_in[1];
    const float* W     = (const float*)d_in[2];
    const float* a     = (const float*)d_in[3];
    float* out = (float*)d_out;

    cudaFuncSetAttribute(k_hgen, cudaFuncAttributeMaxDynamicSharedMemorySize, HG_FLOATS * 4);
    cudaFuncSetAttribute(k_att, cudaFuncAttributeMaxDynamicSharedMemorySize, AT_HALVES * 2);

    k_wa<<<1, 256>>>(W, a);                                   // launch 1
    k_f12<<<BSZ * NN / 8, 256>>>(input);                      // launch 2
    k_maxc<<<BSZ, 256>>>();                                   // launch 3
    k_Z<<<dim3(NN / 128, 8, BSZ), 128>>>(adj);                // launch 4
    k_hgen<<<BSZ * NN / 64, 256, HG_FLOATS * 4>>>(input, W);  // launch 5
    k_att<<<dim3(NN / 128, BSZ), 512, AT_HALVES * 2>>>(adj, out);  // launch 6 (ncu -s 5)
}

// round 8
// speedup vs baseline: 2.8889x; 1.1435x over previous
#include <cuda_runtime.h>
#include <cuda_fp16.h>
#include <cstdint>
#include <math.h>

#define BSZ 4
#define NN 4096
#define FD 256
#define KC 64
#define NCH (NN / KC)
#define ZSPLIT 16
#define LOG2E 1.4426950408889634f

// ---------------- scratch ----------------
__device__ __half g_hnT[BSZ * FD * NN];  // [b][f][j] = h[j,f]/S_j, fp16
__device__ float g_f1[BSZ * NN];
__device__ float g_f2[BSZ * NN];
__device__ float g_c[BSZ * NN];          // lrelu(maxf1 + f2_j), log2 units
__device__ float g_Zp[ZSPLIT][BSZ * NN];

// ---------------- helpers ----------------
__device__ __forceinline__ uint32_t smem_u32(const void* p) {
    uint32_t a;
    asm("{ .reg .u64 t; cvta.to.shared.u64 t, %1; cvt.u32.u64 %0, t; }" : "=r"(a) : "l"(p));
    return a;
}
__device__ __forceinline__ float tf32r(float x) {
    uint32_t r;
    asm("cvt.rna.tf32.f32 %0, %1;" : "=r"(r) : "f"(x));
    return __uint_as_float(r);
}
__device__ __forceinline__ float ex2(float y) {   // MUFU exp2
    float r;
    asm("ex2.approx.ftz.f32 %0, %1;" : "=f"(r) : "f"(y));
    return r;
}
__device__ __forceinline__ void cp16(uint32_t dst, const void* src) {
    asm volatile("cp.async.cg.shared.global [%0], [%1], 16;" :: "r"(dst), "l"(src));
}
#define CP_COMMIT() asm volatile("cp.async.commit_group;" ::: "memory")
#define CP_WAIT0()  asm volatile("cp.async.wait_group 0;" ::: "memory")

__device__ __forceinline__ float fexp2(float y) {  // FMA-pipe 2^y (epilogue use)
    float yr = y + 12582912.0f;
    int n = __float_as_int(yr) - 0x4B400000;
    float r = y - (yr - 12582912.0f);
    float p = fmaf(0.0013333558f, r, 0.0096181291f);
    p = fmaf(p, r, 0.0555041086f);
    p = fmaf(p, r, 0.2402265069f);
    p = fmaf(p, r, 0.6931471806f);
    p = fmaf(p, r, 1.0f);
    return __int_as_float(__float_as_int(p) + (n << 23));
}
__device__ __forceinline__ float felu(float x) {
    float q = fmaf(0.0083333338f, x, 0.0416666679f);
    q = fmaf(q, x, 0.16666667f);
    q = fmaf(q, x, 0.5f);
    q = fmaf(q, x, 1.0f);
    float small = x * q;
    float big = fexp2(x * LOG2E) - 1.0f;
    float neg = (x >= -0.25f) ? small : big;
    return (x > 0.f) ? x : neg;
}
__device__ __forceinline__ void ldsm4(uint32_t* r, uint32_t addr) {
    asm volatile("ldmatrix.sync.aligned.m8n8.x4.shared.b16 {%0,%1,%2,%3}, [%4];"
                 : "=r"(r[0]), "=r"(r[1]), "=r"(r[2]), "=r"(r[3]) : "r"(addr));
}
__device__ __forceinline__ void mma_f16(float* d, const uint32_t* a, const uint32_t* b2) {
    asm volatile(
        "mma.sync.aligned.m16n8k16.row.col.f32.f16.f16.f32 "
        "{%0,%1,%2,%3}, {%4,%5,%6,%7}, {%8,%9}, {%0,%1,%2,%3};"
        : "+f"(d[0]), "+f"(d[1]), "+f"(d[2]), "+f"(d[3])
        : "r"(a[0]), "r"(a[1]), "r"(a[2]), "r"(a[3]), "r"(b2[0]), "r"(b2[1]));
}
__device__ __forceinline__ void mma_tf32(float* d, const uint32_t* a, const uint32_t* bb) {
    asm volatile(
        "mma.sync.aligned.m16n8k8.row.col.f32.tf32.tf32.f32 "
        "{%0,%1,%2,%3}, {%4,%5,%6,%7}, {%8,%9}, {%0,%1,%2,%3};"
        : "+f"(d[0]), "+f"(d[1]), "+f"(d[2]), "+f"(d[3])
        : "r"(a[0]), "r"(a[1]), "r"(a[2]), "r"(a[3]), "r"(bb[0]), "r"(bb[1]));
}

// ---------------------------------------------------------------------------
// L1: fused  v = (W@a)*log2e (per-block, smem)  +  f1 = X.v1, f2 = X.v2
//   512 threads, 64 rows per block
// ---------------------------------------------------------------------------
__global__ __launch_bounds__(512) void k_f12v(const float* __restrict__ X,
                                              const float* __restrict__ W,
                                              const float* __restrict__ a) {
    __shared__ float sa[2 * FD];
    __shared__ float sv[2 * FD];
    const int t = threadIdx.x, lane = t & 31, w = t >> 5;
    sa[t] = a[t];
    __syncthreads();
    if (t < FD) {
        float s1 = 0.f, s2 = 0.f;
        const float* wr = W + (size_t)t * FD;
#pragma unroll 4
        for (int f = 0; f < FD; f++) {
            float wv = wr[f];
            s1 = fmaf(wv, sa[f], s1);
            s2 = fmaf(wv, sa[FD + f], s2);
        }
        sv[t] = s1 * LOG2E;
        sv[FD + t] = s2 * LOG2E;
    }
    __syncthreads();
    const int R0 = blockIdx.x * 64;
#pragma unroll
    for (int rr = 0; rr < 4; rr++) {
        const int row = R0 + w * 4 + rr;
        const float* xr = X + (size_t)row * FD;
        float s1 = 0.f, s2 = 0.f;
#pragma unroll
        for (int k = lane; k < FD; k += 32) {
            float xv = xr[k];
            s1 = fmaf(xv, sv[k], s1);
            s2 = fmaf(xv, sv[FD + k], s2);
        }
#pragma unroll
        for (int o = 16; o; o >>= 1) {
            s1 += __shfl_xor_sync(~0u, s1, o);
            s2 += __shfl_xor_sync(~0u, s2, o);
        }
        if (lane == 0) { g_f1[row] = s1; g_f2[row] = s2; }
    }
}

// ---------------------------------------------------------------------------
// L2: fused  max(f1) + c_j  +  shifted partial sums (MUFU ex2)
//   grid (NN/128, ZSPLIT, BSZ), 128 threads
// ---------------------------------------------------------------------------
__global__ __launch_bounds__(128) void k_Zc(const int* __restrict__ adj) {
    __shared__ float red[128];
    const int b = blockIdx.z;
    const int tid = threadIdx.x;
    const int j = blockIdx.x * 128 + tid;
    const int split = blockIdx.y;
    const int ilen = NN / ZSPLIT;
    const int i0 = split * ilen;

    // block-local max over f1 (L2-cached; cheap)
    float m = -1e30f;
    for (int i = tid; i < NN; i += 128)
        m = fmaxf(m, g_f1[b * NN + i]);
    red[tid] = m;
    __syncthreads();
#pragma unroll
    for (int o = 64; o; o >>= 1) {
        if (tid < o) red[tid] = fmaxf(red[tid], red[tid + o]);
        __syncthreads();
    }
    const float mf = red[0];

    const float f2j = g_f2[b * NN + j];
    float s0 = mf + f2j;
    const float cj = fmaxf(s0, 0.2f * s0);
    if (split == 0) g_c[b * NN + j] = cj;

    const int* ap = adj + ((size_t)b * NN + i0) * NN + j;
    const float* f1p = g_f1 + b * NN + i0;
    float acc = 0.f;
#pragma unroll 8
    for (int i = 0; i < ilen; i++) {
        int mm = ap[(size_t)i * NN];
        float y = f1p[i] + f2j;
        y = fmaxf(y, 0.2f * y) - cj;
        float e = ex2(y);
        acc += (mm > 0) ? e : 0.f;
    }
    g_Zp[split][b * NN + j] = acc;
}

// ---------------------------------------------------------------------------
// L3: hnT[b][f][j] = fp16( (X@W)[j,f] / S_j )  via tf32 mma + smem transpose
// ---------------------------------------------------------------------------
#define HG_ZI 0
#define HG_A 64
#define HG_ASTG (32 * 72)
#define HG_B (64 + 2 * HG_ASTG)
#define HG_BSTG (32 * 264)
#define HG_FLOATS (HG_B + 2 * HG_BSTG)
__global__ void __launch_bounds__(256, 2) k_hgen(const float* __restrict__ X,
                                                 const float* __restrict__ W) {
    extern __shared__ float sm[];
    const uint32_t smb = smem_u32(sm);
    const int t = threadIdx.x, lane = t & 31, wn = t >> 5, g = lane >> 2;
    const int R0 = blockIdx.x * 64;
    const int ia = t & 63, kh = (t >> 6) * 8;
    const int kb = t >> 3, seg = t & 7;

    if (t < 64) {
        float z = 0.f;
#pragma unroll
        for (int s = 0; s < ZSPLIT; s++) z += g_Zp[s][R0 + t];
        sm[HG_ZI + t] = 1.0f / z;
    }

    const float* xrow = X + (size_t)(R0 + ia) * FD + kh;
    {
        const float* src = W + (size_t)kb * FD + seg * 4;
        uint32_t dst = smb + (HG_B + kb * 264 + seg * 4) * 4;
#pragma unroll
        for (int q = 0; q < 8; q++) cp16(dst + q * 128, src + q * 32);
        CP_COMMIT();
    }

    float acc[4][4][4] = {};
    for (int c = 0; c < 8; c++) {
        const int aoff = HG_A + (c & 1) * HG_ASTG;
        const int boff = HG_B + (c & 1) * HG_BSTG;
        float4 x0 = *(const float4*)(xrow + c * 32);
        float4 x1 = *(const float4*)(xrow + c * 32 + 4);
        float e[8] = {x0.x, x0.y, x0.z, x0.w, x1.x, x1.y, x1.z, x1.w};
#pragma unroll
        for (int q = 0; q < 8; q++)
            sm[aoff + (kh + q) * 72 + ia] = tf32r(e[q]);
        CP_WAIT0();
        __syncthreads();
        if (c < 7) {
            const float* src = W + (size_t)((c + 1) * 32 + kb) * FD + seg * 4;
            uint32_t dst = smb + (HG_B + ((c + 1) & 1) * HG_BSTG + kb * 264 + seg * 4) * 4;
#pragma unroll
            for (int q = 0; q < 8; q++) cp16(dst + q * 128, src + q * 32);
            CP_COMMIT();
        }
        const uint32_t* smu = (const uint32_t*)sm;
#pragma unroll
        for (int kf = 0; kf < 4; kf++) {
            const int krow = kf * 8 + (lane & 3);
            uint32_t a[4][4];
#pragma unroll
            for (int mf = 0; mf < 4; mf++) {
                int base = aoff + krow * 72 + mf * 16 + g;
                a[mf][0] = smu[base];
                a[mf][1] = smu[base + 8];
                a[mf][2] = smu[base + 4 * 72];
                a[mf][3] = smu[base + 4 * 72 + 8];
            }
            uint32_t bf[4][2];
#pragma unroll
            for (int nf = 0; nf < 4; nf++) {
                int base = boff + krow * 264 + wn * 32 + nf * 8 + g;
                bf[nf][0] = smu[base];
                bf[nf][1] = smu[base + 4 * 264];
            }
#pragma unroll
            for (int mf = 0; mf < 4; mf++)
#pragma unroll
                for (int nf = 0; nf < 4; nf++)
                    mma_tf32(acc[mf][nf], a[mf], bf[nf]);
        }
    }

    __syncthreads();
    __half* Ts = (__half*)(sm + HG_B);           // [f=256][j=64], stride 72 halves
#pragma unroll
    for (int mf = 0; mf < 4; mf++) {
        const int r0 = mf * 16 + g;
        const float zi0 = sm[HG_ZI + r0], zi1 = sm[HG_ZI + r0 + 8];
#pragma unroll
        for (int nf = 0; nf < 4; nf++) {
            const int c0 = wn * 32 + nf * 8 + 2 * (lane & 3);
            Ts[(c0)     * 72 + r0]     = __float2half_rn(acc[mf][nf][0] * zi0);
            Ts[(c0 + 1) * 72 + r0]     = __float2half_rn(acc[mf][nf][1] * zi0);
            Ts[(c0)     * 72 + r0 + 8] = __float2half_rn(acc[mf][nf][2] * zi1);
            Ts[(c0 + 1) * 72 + r0 + 8] = __float2half_rn(acc[mf][nf][3] * zi1);
        }
    }
    __syncthreads();
    const int b = R0 >> 12, jloc = R0 & (NN - 1);
    __half* dst = g_hnT + ((size_t)b * FD + t) * NN + jloc;
    const uint4* srcv = (const uint4*)(Ts + t * 72);
#pragma unroll
    for (int q = 0; q < 8; q++)
        ((uint4*)dst)[q] = srcv[q];
}

// ---------------------------------------------------------------------------
// L4: out = elu( E' @ B' )  fp16 mma, 512 thr, KC=64 chunks (1 sync / 64 j)
//   CTA 128(i) x 256(f); warp tile 32x64
// ---------------------------------------------------------------------------
#define AT_STR 72                        // halves (64 data + 8 pad)
#define AT_ASTG (128 * AT_STR)           // 9216 halves/stage
#define AT_B0 (2 * AT_ASTG)              // 18432
#define AT_BSTG (256 * AT_STR)           // 18432 halves/stage
#define AT_HALVES (AT_B0 + 2 * AT_BSTG)  // 55296 (108 KB)
__global__ void __launch_bounds__(512, 1) k_att(const int* __restrict__ adj,
                                                float* __restrict__ out) {
    extern __shared__ __half sh[];
    const uint32_t smb = smem_u32(sh);
    const int t = threadIdx.x, lane = t & 31, wid = t >> 5;
    const int wm = wid >> 2, wn = wid & 3;
    const int g = lane >> 2, c2 = lane & 3;
    const int b = blockIdx.y;
    const int i0 = blockIdx.x * 128;

    // A-builder: thread builds 16 j of one row
    const int ia = t & 127;
    const int kh = (t >> 7) * 16;        // 0,16,32,48
    const int* ap = adj + ((size_t)(b * NN + i0 + ia)) * NN + kh;
    const float* f2p = g_f2 + b * NN + kh;
    const float* cjp = g_c + b * NN + kh;
    const float f1v = g_f1[b * NN + i0 + ia];
    const __half* hT = g_hnT + (size_t)b * FD * NN;

    // B-loader: thread pair covers one f-row (64 halves)
    const int fr = t >> 1, sg = t & 1;

    const uint32_t aBase = smb + (uint32_t)((wm * 32 + (lane & 15)) * AT_STR + (lane >> 4) * 8) * 2;
    const uint32_t bBase = smb + (uint32_t)((wn * 64 + (lane & 7) + (lane >> 4) * 8) * AT_STR
                                            + ((lane >> 3) & 1) * 8) * 2;

    // ---- prologue: B(0), adj(0), A(0) ----
    {
        const __half* src = hT + (size_t)fr * NN + sg * 32;
        uint32_t dst = smb + (AT_B0 + fr * AT_STR) * 2 + sg * 64;
#pragma unroll
        for (int q = 0; q < 4; q++) cp16(dst + q * 16, src + q * 8);
        CP_COMMIT();
    }
    int4 m[4];
#pragma unroll
    for (int q = 0; q < 4; q++) m[q] = ((const int4*)ap)[q];
    {
        int mm[16] = {m[0].x, m[0].y, m[0].z, m[0].w, m[1].x, m[1].y, m[1].z, m[1].w,
                      m[2].x, m[2].y, m[2].z, m[2].w, m[3].x, m[3].y, m[3].z, m[3].w};
        float ev[16];
#pragma unroll
        for (int r = 0; r < 16; r++) {
            float s = f1v + f2p[r];
            float y = fmaxf(s, 0.2f * s) - cjp[r];
            ev[r] = (mm[r] > 0) ? ex2(y) : 0.f;
        }
        __half2 h2[8];
#pragma unroll
        for (int p = 0; p < 8; p++) h2[p] = __floats2half2_rn(ev[2 * p], ev[2 * p + 1]);
        *(uint4*)(sh + ia * AT_STR + kh) = *(uint4*)(&h2[0]);
        *(uint4*)(sh + ia * AT_STR + kh + 8) = *(uint4*)(&h2[4]);
    }
    CP_WAIT0();
    __syncthreads();

    float acc[2][8][4] = {};

    for (int c = 0; c < NCH; c++) {
        // ---- issue next-chunk loads (overlap with mma) ----
        if (c + 1 < NCH) {
            const __half* src = hT + (size_t)fr * NN + (c + 1) * KC + sg * 32;
            uint32_t dst = smb + (AT_B0 + ((c + 1) & 1) * AT_BSTG + fr * AT_STR) * 2 + sg * 64;
#pragma unroll
            for (int q = 0; q < 4; q++) cp16(dst + q * 16, src + q * 8);
            CP_COMMIT();
#pragma unroll
            for (int q = 0; q < 4; q++)
                m[q] = *(const int4*)(ap + (c + 1) * KC + q * 4);
        }

        // ---- mma(c): 4 k-frags of 16 ----
        const uint32_t aS = aBase + (c & 1) * (AT_ASTG * 2);
        const uint32_t bS = bBase + ((c & 1) * AT_BSTG + AT_B0) * 2;
#pragma unroll
        for (int kf = 0; kf < 4; kf++) {
            uint32_t af[2][4];
#pragma unroll
            for (int mf = 0; mf < 2; mf++)
                ldsm4(af[mf], aS + mf * (16 * AT_STR * 2) + kf * 32);
            uint32_t bf[4][4];
#pragma unroll
            for (int nfp = 0; nfp < 4; nfp++)
                ldsm4(bf[nfp], bS + nfp * (16 * AT_STR * 2) + kf * 32);
#pragma unroll
            for (int mf = 0; mf < 2; mf++)
#pragma unroll
                for (int nf = 0; nf < 8; nf++)
                    mma_f16(acc[mf][nf], af[mf], &bf[nf >> 1][(nf & 1) * 2]);
        }

        // ---- build A(c+1) (MUFU+FMA; overlaps tensor) ----
        if (c + 1 < NCH) {
            const int j1 = (c + 1) * KC;
            int mm[16] = {m[0].x, m[0].y, m[0].z, m[0].w, m[1].x, m[1].y, m[1].z, m[1].w,
                          m[2].x, m[2].y, m[2].z, m[2].w, m[3].x, m[3].y, m[3].z, m[3].w};
            float ev[16];
#pragma unroll
            for (int r = 0; r < 16; r++) {
                float s = f1v + f2p[j1 + r];
                float y = fmaxf(s, 0.2f * s) - cjp[j1 + r];
                ev[r] = (mm[r] > 0) ? ex2(y) : 0.f;
            }
            __half2 h2[8];
#pragma unroll
            for (int p = 0; p < 8; p++) h2[p] = __floats2half2_rn(ev[2 * p], ev[2 * p + 1]);
            __half* sA = sh + ((c + 1) & 1) * AT_ASTG + ia * AT_STR + kh;
            *(uint4*)(sA) = *(uint4*)(&h2[0]);
            *(uint4*)(sA + 8) = *(uint4*)(&h2[4]);

            CP_WAIT0();
            __syncthreads();
        }
    }

    // ---- epilogue ----
#pragma unroll
    for (int mf = 0; mf < 2; mf++) {
        const int r = i0 + wm * 32 + mf * 16 + g;
#pragma unroll
        for (int nf = 0; nf < 8; nf++) {
            const int col = wn * 64 + nf * 8 + 2 * c2;
            float2 p0 = make_float2(felu(acc[mf][nf][0]), felu(acc[mf][nf][1]));
            float2 p1 = make_float2(felu(acc[mf][nf][2]), felu(acc[mf][nf][3]));
            *(float2*)(out + ((size_t)(b * NN + r)) * FD + col) = p0;
            *(float2*)(out + ((size_t)(b * NN + r + 8)) * FD + col) = p1;
        }
    }
}

// ---------------------------------------------------------------------------
extern "C" void kernel_launch(void* const* d_in, const int* in_sizes, int n_in,
                              void* d_out, int out_size) {
    const float* input = (const float*)d_in[0];
    const int*   adj   = (const int*)d_in[1];
    const float* W     = (const float*)d_in[2];
    const float* a     = (const float*)d_in[3];
    float* out = (float*)d_out;

    cudaFuncSetAttribute(k_hgen, cudaFuncAttributeMaxDynamicSharedMemorySize, HG_FLOATS * 4);
    cudaFuncSetAttribute(k_att, cudaFuncAttributeMaxDynamicSharedMemorySize, AT_HALVES * 2);

    k_f12v<<<BSZ * NN / 64, 512>>>(input, W, a);                   // launch 1
    k_Zc<<<dim3(NN / 128, ZSPLIT, BSZ), 128>>>(adj);               // launch 2
    k_hgen<<<BSZ * NN / 64, 256, HG_FLOATS * 4>>>(input, W);       // launch 3
    k_att<<<dim3(NN / 128, BSZ), 512, AT_HALVES * 2>>>(adj, out);  // launch 4 (profiled)
}